// round 9
// baseline (speedup 1.0000x reference)
#include <cuda_runtime.h>

// ---------------------------------------------------------------------------
// Problem constants
// ---------------------------------------------------------------------------
constexpr int Bb  = 2048;
constexpr int Nn  = 8;
constexpr int Tt  = 20;
constexpr int Mm  = Bb * Nn;        // 16384 sequences
constexpr int HS  = 128;
constexpr int G3  = 3 * HS;         // 384
constexpr int RT  = Mm * Tt;        // 327680 rows (m*T + t)
constexpr int WT2P = 776;           // k-pair weight row pitch: 192 quads *4 + 8 pad
constexpr int DPP = 132;            // dup tile pitch (64 k dup -> 128 floats + 4 pad)
constexpr int OUT0 = Mm * 64;       // first output section ("out")

// Scratch as device globals (no runtime allocation allowed)
__device__ float g_gi[(size_t)RT * G3];   // 503 MB input-gate preactivations
__device__ float g_ys[(size_t)RT * HS];   // 168 MB layer outputs (reused per layer)

typedef unsigned long long ULL;

// packed f32x2 FMA (full fp32 rate on sm_103a requires fma.rn.f32x2)
__device__ __forceinline__ void fma2(ULL& d, ULL a, ULL b) {
    asm("fma.rn.f32x2 %0, %1, %2, %0;" : "+l"(d) : "l"(a), "l"(b));
}
__device__ __forceinline__ float2 unpk(ULL v) {
    float2 f; asm("mov.b64 {%0, %1}, %2;" : "=f"(f.x), "=f"(f.y) : "l"(v)); return f;
}
__device__ __forceinline__ float sigm(float x) { return 1.0f / (1.0f + __expf(-x)); }
__device__ __forceinline__ float tanh_(float x) { return 1.0f - 2.0f / (__expf(2.0f * x) + 1.0f); }

// Transpose W (G3 x K, row-major) into the k-pair-interleaved quad layout:
//   Wt2[k>>1][4*(g>>1) + 2*(k&1) + (g&1)] = W[g][k]
// One LDS.128 at (k2, quad p) yields {W(k,2p),W(k,2p+1),W(k+1,2p),W(k+1,2p+1)}.
template <int K, int NT>
__device__ __forceinline__ void fill_Wt2(float* Wt2, const float* __restrict__ W, int tid) {
    for (int g = tid; g < G3; g += NT) {
        const float* src = W + (size_t)g * K;
        float* dcol = Wt2 + 4 * (g >> 1) + (g & 1);
#pragma unroll 4
        for (int k0 = 0; k0 < K; k0 += 4) {
            float4 w = *(const float4*)(src + k0);
            float* d = dcol + (k0 >> 1) * WT2P;
            d[0] = w.x; d[2] = w.y;
            d[WT2P] = w.z; d[WT2P + 2] = w.w;
        }
    }
}

// ---------------------------------------------------------------------------
// gi GEMM:  gi[r,:] = xs[r,:] @ Wih^T + bih        (r = m*T + t)
// 512 threads, 64 rows/CTA. Thread: 8 rows x 1 col-pair x 3 gates = 24 accs.
// 16 warps = 4/SMSP. x tile dup over a 64-k chunk ([row][2k]); weights in the
// quad layout -> per k-pair: 3 weight LDS.128 + 8 broadcast h LDS.128 + 48 fma2.
// K=64 fuses the embedding; K=128 reads g_ys.
// ---------------------------------------------------------------------------
template <int K>
__global__ __launch_bounds__(512) void gi_gemm(
    const float* __restrict__ Wih, const float* __restrict__ bih,
    const float* __restrict__ x,   const float* __restrict__ pea,
    const float* __restrict__ pet, const float* __restrict__ embW,
    const float* __restrict__ embB)
{
    extern __shared__ float sm[];
    float* Wt2 = sm;                       // [K/2][WT2P]
    float* xT  = sm + (K / 2) * WT2P;      // [64][DPP]  dup over current 64-k chunk

    int tid = threadIdx.x;
    fill_Wt2<K, 512>(Wt2, Wih, tid);

    int rg = tid >> 6;              // row-group 0..7 (8 rows each)
    int pp = tid & 63;              // column-pair 0..63
    int c2 = 2 * pp;
    int r0 = rg * 8;
    int row0 = blockIdx.x * 64;

    ULL aR[8], aZ[8], aN[8];
#pragma unroll
    for (int j = 0; j < 8; ++j) { aR[j] = 0ULL; aZ[j] = 0ULL; aN[j] = 0ULL; }

    constexpr int NCH = K / 64;
    for (int ch = 0; ch < NCH; ++ch) {
        __syncthreads();   // Wt2 ready / previous chunk's xT reads done
        // fill xT (duplicated): 64 rows x 16 float4 reads
        for (int idx = tid; idx < 64 * 16; idx += 512) {
            int r = idx >> 4, kq = idx & 15;
            float4 v;
            if (K == 64) {
                // fused embedding: v_e = relu(emb_b + (x0+pe)W[e,0] + (x1+pe)W[e,1])
                int row = row0 + r;
                int t = row % Tt;
                int n = (row / Tt) & 7;
                float pe = __ldg(pet + t) + __ldg(pea + n);
                float2 xv = *(const float2*)(x + (size_t)row * 2);
                float x0 = xv.x + pe, x1 = xv.y + pe;
                float4 w0 = __ldg((const float4*)(embW + 8 * kq));
                float4 w1 = __ldg((const float4*)(embW + 8 * kq + 4));
                float4 b4 = __ldg((const float4*)(embB + 4 * kq));
                v.x = fmaxf(fmaf(x0, w0.x, fmaf(x1, w0.y, b4.x)), 0.0f);
                v.y = fmaxf(fmaf(x0, w0.z, fmaf(x1, w0.w, b4.y)), 0.0f);
                v.z = fmaxf(fmaf(x0, w1.x, fmaf(x1, w1.y, b4.z)), 0.0f);
                v.w = fmaxf(fmaf(x0, w1.z, fmaf(x1, w1.w, b4.w)), 0.0f);
            } else {
                v = *(const float4*)(g_ys + (size_t)(row0 + r) * K + ch * 64 + 4 * kq);
            }
            float* d = xT + r * DPP + 8 * kq;
            *(float4*)(d)     = make_float4(v.x, v.x, v.y, v.y);
            *(float4*)(d + 4) = make_float4(v.z, v.z, v.w, v.w);
        }
        __syncthreads();

#pragma unroll 2
        for (int k2 = 0; k2 < 32; ++k2) {           // k-pairs within chunk
            const float* wrow = Wt2 + (size_t)(ch * 32 + k2) * WT2P + 4 * pp;
            ulonglong2 wr = *(const ulonglong2*)(wrow);          // gate r: (w_k | w_k1)
            ulonglong2 wz = *(const ulonglong2*)(wrow + 256);    // gate z
            ulonglong2 wn = *(const ulonglong2*)(wrow + 512);    // gate n
            const float* hb = xT + r0 * DPP + 4 * k2;
#pragma unroll
            for (int j = 0; j < 8; ++j) {
                ulonglong2 h = *(const ulonglong2*)(hb + j * DPP);  // (hk hk | hk1 hk1)
                fma2(aR[j], h.x, wr.x); fma2(aR[j], h.y, wr.y);
                fma2(aZ[j], h.x, wz.x); fma2(aZ[j], h.y, wz.y);
                fma2(aN[j], h.x, wn.x); fma2(aN[j], h.y, wn.y);
            }
        }
    }

    // epilogue: bias + coalesced STG.64
    {
        float2 b2;
        b2 = *(const float2*)(bih + c2);
#pragma unroll
        for (int j = 0; j < 8; ++j) {
            float2 p = unpk(aR[j]); p.x += b2.x; p.y += b2.y;
            *(float2*)(g_gi + (size_t)(row0 + r0 + j) * G3 + c2) = p;
        }
        b2 = *(const float2*)(bih + 128 + c2);
#pragma unroll
        for (int j = 0; j < 8; ++j) {
            float2 p = unpk(aZ[j]); p.x += b2.x; p.y += b2.y;
            *(float2*)(g_gi + (size_t)(row0 + r0 + j) * G3 + 128 + c2) = p;
        }
        b2 = *(const float2*)(bih + 256 + c2);
#pragma unroll
        for (int j = 0; j < 8; ++j) {
            float2 p = unpk(aN[j]); p.x += b2.x; p.y += b2.y;
            *(float2*)(g_gi + (size_t)(row0 + r0 + j) * G3 + 256 + c2) = p;
        }
    }
}

// ---------------------------------------------------------------------------
// GRU recurrent scan for one layer.
// 256 CTAs x 512 threads x 64 rows; all 20 steps on-chip. 16 warps = 4/SMSP.
// smem: Whh quad layout [64][WT2P] + ONE chunk-swapped dup h buffer [64][DPP]:
//   owners of h-cols [0,64) refill it at the end of each step (chunk0),
//   owners of [64,128) refill it between the two half-k loops (chunk1).
// Thread: 8 rows x 1 col-pair x 3 gates. Per k-pair: 3 wt LDS.128 + 8 h
// LDS.128 + 48 fma2 -> 320 wf/SM < 384 FMA cyc (fma-bound).
// ---------------------------------------------------------------------------
__global__ __launch_bounds__(512) void scan_kernel(
    const float* __restrict__ Whh, const float* __restrict__ bhh,
    float* __restrict__ hid)
{
    extern __shared__ float sm[];
    float* Wt2 = sm;                 // [64][WT2P]
    float* hB  = sm + 64 * WT2P;     // [64][DPP]  dup buffer (one 64-k chunk)

    int tid = threadIdx.x;
    fill_Wt2<HS, 512>(Wt2, Whh, tid);
    for (int i = tid; i < 64 * DPP; i += 512) hB[i] = 0.0f;   // chunk0 of h0 = 0

    int rg = tid >> 6;           // row-group 0..7 (8 rows each)
    int pp = tid & 63;           // column-pair 0..63 (h-cols c2, c2+1)
    int c2 = 2 * pp;
    int r0 = rg * 8;
    int m0 = blockIdx.x * 64;

    const float2 bR = *(const float2*)(bhh + c2);
    const float2 bZ = *(const float2*)(bhh + 128 + c2);
    const float2 bN = *(const float2*)(bhh + 256 + c2);

    float2 hreg[8];
#pragma unroll
    for (int j = 0; j < 8; ++j) hreg[j] = make_float2(0.0f, 0.0f);

    __syncthreads();

    for (int t = 0; t < Tt; ++t) {
        ULL aR[8], aZ[8], aN[8];
#pragma unroll
        for (int j = 0; j < 8; ++j) { aR[j] = 0ULL; aZ[j] = 0ULL; aN[j] = 0ULL; }

        // ---- chunk 0: k in [0,64), buffer holds dup h[0:64) ----
#pragma unroll 2
        for (int k2 = 0; k2 < 32; ++k2) {
            const float* wrow = Wt2 + (size_t)k2 * WT2P + 4 * pp;
            ulonglong2 wr = *(const ulonglong2*)(wrow);
            ulonglong2 wz = *(const ulonglong2*)(wrow + 256);
            ulonglong2 wn = *(const ulonglong2*)(wrow + 512);
            const float* hb = hB + r0 * DPP + 4 * k2;
#pragma unroll
            for (int j = 0; j < 8; ++j) {
                ulonglong2 h = *(const ulonglong2*)(hb + j * DPP);
                fma2(aR[j], h.x, wr.x); fma2(aR[j], h.y, wr.y);
                fma2(aZ[j], h.x, wz.x); fma2(aZ[j], h.y, wz.y);
                fma2(aN[j], h.x, wn.x); fma2(aN[j], h.y, wn.y);
            }
        }
        __syncthreads();   // B1: chunk0 reads done

        // owners of h-cols [64,128) write dup chunk1 into the buffer
        if (pp >= 32) {
            int off = 4 * pp - 128;          // float offset in row
#pragma unroll
            for (int j = 0; j < 8; ++j)
                *(float4*)(hB + (r0 + j) * DPP + off) =
                    make_float4(hreg[j].x, hreg[j].x, hreg[j].y, hreg[j].y);
        }
        __syncthreads();   // B2: chunk1 written

        // ---- chunk 1: k in [64,128) ----
#pragma unroll 2
        for (int k2 = 0; k2 < 32; ++k2) {
            const float* wrow = Wt2 + (size_t)(32 + k2) * WT2P + 4 * pp;
            ulonglong2 wr = *(const ulonglong2*)(wrow);
            ulonglong2 wz = *(const ulonglong2*)(wrow + 256);
            ulonglong2 wn = *(const ulonglong2*)(wrow + 512);
            const float* hb = hB + r0 * DPP + 4 * k2;
#pragma unroll
            for (int j = 0; j < 8; ++j) {
                ulonglong2 h = *(const ulonglong2*)(hb + j * DPP);
                fma2(aR[j], h.x, wr.x); fma2(aR[j], h.y, wr.y);
                fma2(aZ[j], h.x, wz.x); fma2(aZ[j], h.y, wz.y);
                fma2(aN[j], h.x, wn.x); fma2(aN[j], h.y, wn.y);
            }
        }
        __syncthreads();   // B3: chunk1 reads done

        // ---- gates + state update ----
#pragma unroll
        for (int j = 0; j < 8; ++j) {
            size_t rbase = (size_t)(m0 + r0 + j) * Tt + t;
            const float* gp = g_gi + rbase * G3;
            float2 giR = *(const float2*)(gp + c2);
            float2 giZ = *(const float2*)(gp + 128 + c2);
            float2 giN = *(const float2*)(gp + 256 + c2);
            float2 ghR = unpk(aR[j]), ghZ = unpk(aZ[j]), ghN = unpk(aN[j]);
            float rv0 = sigm(giR.x + ghR.x + bR.x);
            float rv1 = sigm(giR.y + ghR.y + bR.y);
            float zv0 = sigm(giZ.x + ghZ.x + bZ.x);
            float zv1 = sigm(giZ.y + ghZ.y + bZ.y);
            float nv0 = tanh_(giN.x + rv0 * (ghN.x + bN.x));
            float nv1 = tanh_(giN.y + rv1 * (ghN.y + bN.y));
            float hn0 = (1.0f - zv0) * nv0 + zv0 * hreg[j].x;
            float hn1 = (1.0f - zv1) * nv1 + zv1 * hreg[j].y;
            hreg[j] = make_float2(hn0, hn1);
            *(float2*)(g_ys + rbase * HS + c2) = hreg[j];
        }
        // owners of h-cols [0,64) write dup chunk0 for the next step
        if (pp < 32) {
            int off = 4 * pp;
#pragma unroll
            for (int j = 0; j < 8; ++j)
                *(float4*)(hB + (r0 + j) * DPP + off) =
                    make_float4(hreg[j].x, hreg[j].x, hreg[j].y, hreg[j].y);
        }
        __syncthreads();   // B4: chunk0 ready for next step
    }

    // hidden output: final h of rows with m % 8 == 7 -> row j == 7 in each group
    int b = (m0 + r0 + 7) >> 3;
    *(float2*)(hid + (size_t)b * HS + c2) = hreg[7];
}

// ---------------------------------------------------------------------------
// Output projection  out[m, e] = ys_last[m, :] @ out_W[e, :] + out_b[e]
// ---------------------------------------------------------------------------
__global__ __launch_bounds__(256) void out_kernel(
    const float* __restrict__ oW, const float* __restrict__ ob,
    float* __restrict__ out)
{
    __shared__ float sW[128 * 64];   // transposed [k][e]
    int tid = threadIdx.x;
    for (int idx = tid; idx < 64 * 128; idx += 256) {
        int e = idx >> 7, k = idx & 127;
        sW[k * 64 + e] = oW[idx];
    }
    __syncthreads();
    int gid = blockIdx.x * 256 + tid;       // gid = m*64 + e
    int e = gid & 63;
    int m = gid >> 6;
    const float* ys = g_ys + ((size_t)m * Tt + (Tt - 1)) * HS;
    float acc = ob[e];
#pragma unroll 8
    for (int k = 0; k < 128; ++k) acc = fmaf(ys[k], sW[k * 64 + e], acc);
    out[gid] = acc;
}

// ---------------------------------------------------------------------------
// Launch
// ---------------------------------------------------------------------------
extern "C" void kernel_launch(void* const* d_in, const int* in_sizes, int n_in,
                              void* d_out, int out_size) {
    const float* x    = (const float*)d_in[0];
    const float* pea  = (const float*)d_in[1];
    const float* pet  = (const float*)d_in[2];
    const float* embW = (const float*)d_in[3];
    const float* embB = (const float*)d_in[4];
    const float* Wih0 = (const float*)d_in[5];
    const float* WihR = (const float*)d_in[6];   // (2, 384, 128)
    const float* Whh  = (const float*)d_in[7];   // (3, 384, 128)
    const float* bih  = (const float*)d_in[8];   // (3, 384)
    const float* bhh  = (const float*)d_in[9];   // (3, 384)
    const float* outW = (const float*)d_in[10];  // (64, 128)
    const float* outB = (const float*)d_in[11];

    float* out = (float*)d_out;                  // [Mm*64]
    float* hid = out + OUT0;                     // [3][Bb][HS]

    const int smem64   = 32 * WT2P * 4 + 64 * DPP * 4;  //  99328 + 33792 = 133120
    const int smem128  = 64 * WT2P * 4 + 64 * DPP * 4;  // 198656 + 33792 = 232448
    const int smemScan = smem128;                       // 232448 (= 227 KB cap)
    cudaFuncSetAttribute(gi_gemm<64>,  cudaFuncAttributeMaxDynamicSharedMemorySize, smem64);
    cudaFuncSetAttribute(gi_gemm<128>, cudaFuncAttributeMaxDynamicSharedMemorySize, smem128);
    cudaFuncSetAttribute(scan_kernel,  cudaFuncAttributeMaxDynamicSharedMemorySize, smemScan);

    // layer 0 (embedding fused into the gi x-tile fill)
    gi_gemm<64><<<RT / 64, 512, smem64>>>(Wih0, bih, x, pea, pet, embW, embB);
    scan_kernel<<<Mm / 64, 512, smemScan>>>(Whh, bhh, hid);
    // layer 1
    gi_gemm<128><<<RT / 64, 512, smem128>>>(WihR, bih + G3, x, pea, pet, embW, embB);
    scan_kernel<<<Mm / 64, 512, smemScan>>>(Whh + (size_t)G3 * HS, bhh + G3,
                                            hid + (size_t)Bb * HS);
    // layer 2
    gi_gemm<128><<<RT / 64, 512, smem128>>>(WihR + (size_t)G3 * HS, bih + 2 * G3,
                                            x, pea, pet, embW, embB);
    scan_kernel<<<Mm / 64, 512, smemScan>>>(Whh + (size_t)2 * G3 * HS, bhh + 2 * G3,
                                            hid + (size_t)2 * Bb * HS);

    out_kernel<<<(Mm * 64) / 256, 256>>>(outW, outB, out);
}

// round 10
// speedup vs baseline: 1.0510x; 1.0510x over previous
#include <cuda_runtime.h>

// ---------------------------------------------------------------------------
// Problem constants
// ---------------------------------------------------------------------------
constexpr int Bb  = 2048;
constexpr int Nn  = 8;
constexpr int Tt  = 20;
constexpr int Mm  = Bb * Nn;        // 16384 sequences
constexpr int HS  = 128;
constexpr int G3  = 3 * HS;         // 384
constexpr int RT  = Mm * Tt;        // 327680 rows (m*T + t)
constexpr int WT2P = 776;           // k-pair weight row pitch: 192 quads *4 + 8 pad
constexpr int DPP = 132;            // dup tile pitch (64 k dup -> 128 floats + 4 pad)
constexpr int OUT0 = Mm * 64;       // first output section ("out")

// Scratch as device globals (no runtime allocation allowed)
__device__ float g_gi[(size_t)RT * G3];   // 503 MB input-gate preactivations
__device__ float g_ys[(size_t)RT * HS];   // 168 MB layer outputs (reused per layer)

typedef unsigned long long ULL;

// packed f32x2 FMA (full fp32 rate on sm_103a requires fma.rn.f32x2)
__device__ __forceinline__ void fma2(ULL& d, ULL a, ULL b) {
    asm("fma.rn.f32x2 %0, %1, %2, %0;" : "+l"(d) : "l"(a), "l"(b));
}
__device__ __forceinline__ float2 unpk(ULL v) {
    float2 f; asm("mov.b64 {%0, %1}, %2;" : "=f"(f.x), "=f"(f.y) : "l"(v)); return f;
}
__device__ __forceinline__ float sigm(float x) { return 1.0f / (1.0f + __expf(-x)); }
__device__ __forceinline__ float tanh_(float x) { return 1.0f - 2.0f / (__expf(2.0f * x) + 1.0f); }

// Transpose W (G3 x K, row-major) into the k-pair-interleaved quad layout:
//   Wt2[k>>1][4*(g>>1) + 2*(k&1) + (g&1)] = W[g][k]
// One LDS.128 at (k2, quad p) yields {W(k,2p),W(k,2p+1),W(k+1,2p),W(k+1,2p+1)}.
template <int K, int NT>
__device__ __forceinline__ void fill_Wt2(float* Wt2, const float* __restrict__ W, int tid) {
    for (int g = tid; g < G3; g += NT) {
        const float* src = W + (size_t)g * K;
        float* dcol = Wt2 + 4 * (g >> 1) + (g & 1);
#pragma unroll 4
        for (int k0 = 0; k0 < K; k0 += 4) {
            float4 w = *(const float4*)(src + k0);
            float* d = dcol + (k0 >> 1) * WT2P;
            d[0] = w.x; d[2] = w.y;
            d[WT2P] = w.z; d[WT2P + 2] = w.w;
        }
    }
}

// ---------------------------------------------------------------------------
// gi GEMM:  gi[r,:] = xs[r,:] @ Wih^T + bih        (r = m*T + t)
// 512 threads, 64 rows/CTA. Thread: 8 rows x 1 col-pair x 3 gates = 24 accs.
// 16 warps = 4/SMSP. x tile dup over a 64-k chunk ([row][2k]); weights in the
// quad layout -> per k-pair: 3 weight LDS.128 + 8 broadcast h LDS.128 + 48 fma2.
// K=64 fuses the embedding; K=128 reads g_ys.
// ---------------------------------------------------------------------------
template <int K>
__global__ __launch_bounds__(512) void gi_gemm(
    const float* __restrict__ Wih, const float* __restrict__ bih,
    const float* __restrict__ x,   const float* __restrict__ pea,
    const float* __restrict__ pet, const float* __restrict__ embW,
    const float* __restrict__ embB)
{
    extern __shared__ float sm[];
    float* Wt2 = sm;                       // [K/2][WT2P]
    float* xT  = sm + (K / 2) * WT2P;      // [64][DPP]  dup over current 64-k chunk

    int tid = threadIdx.x;
    fill_Wt2<K, 512>(Wt2, Wih, tid);

    int rg = tid >> 6;              // row-group 0..7 (8 rows each)
    int pp = tid & 63;              // column-pair 0..63
    int c2 = 2 * pp;
    int r0 = rg * 8;
    int row0 = blockIdx.x * 64;

    ULL aR[8], aZ[8], aN[8];
#pragma unroll
    for (int j = 0; j < 8; ++j) { aR[j] = 0ULL; aZ[j] = 0ULL; aN[j] = 0ULL; }

    constexpr int NCH = K / 64;
    for (int ch = 0; ch < NCH; ++ch) {
        __syncthreads();   // Wt2 ready / previous chunk's xT reads done
        // fill xT (duplicated): 64 rows x 16 float4 reads
        for (int idx = tid; idx < 64 * 16; idx += 512) {
            int r = idx >> 4, kq = idx & 15;
            float4 v;
            if (K == 64) {
                // fused embedding: v_e = relu(emb_b + (x0+pe)W[e,0] + (x1+pe)W[e,1])
                int row = row0 + r;
                int t = row % Tt;
                int n = (row / Tt) & 7;
                float pe = __ldg(pet + t) + __ldg(pea + n);
                float2 xv = *(const float2*)(x + (size_t)row * 2);
                float x0 = xv.x + pe, x1 = xv.y + pe;
                float4 w0 = __ldg((const float4*)(embW + 8 * kq));
                float4 w1 = __ldg((const float4*)(embW + 8 * kq + 4));
                float4 b4 = __ldg((const float4*)(embB + 4 * kq));
                v.x = fmaxf(fmaf(x0, w0.x, fmaf(x1, w0.y, b4.x)), 0.0f);
                v.y = fmaxf(fmaf(x0, w0.z, fmaf(x1, w0.w, b4.y)), 0.0f);
                v.z = fmaxf(fmaf(x0, w1.x, fmaf(x1, w1.y, b4.z)), 0.0f);
                v.w = fmaxf(fmaf(x0, w1.z, fmaf(x1, w1.w, b4.w)), 0.0f);
            } else {
                v = *(const float4*)(g_ys + (size_t)(row0 + r) * K + ch * 64 + 4 * kq);
            }
            float* d = xT + r * DPP + 8 * kq;
            *(float4*)(d)     = make_float4(v.x, v.x, v.y, v.y);
            *(float4*)(d + 4) = make_float4(v.z, v.z, v.w, v.w);
        }
        __syncthreads();

#pragma unroll 2
        for (int k2 = 0; k2 < 32; ++k2) {           // k-pairs within chunk
            const float* wrow = Wt2 + (size_t)(ch * 32 + k2) * WT2P + 4 * pp;
            ulonglong2 wr = *(const ulonglong2*)(wrow);          // gate r: (w_k | w_k1)
            ulonglong2 wz = *(const ulonglong2*)(wrow + 256);    // gate z
            ulonglong2 wn = *(const ulonglong2*)(wrow + 512);    // gate n
            const float* hb = xT + r0 * DPP + 4 * k2;
#pragma unroll
            for (int j = 0; j < 8; ++j) {
                ulonglong2 h = *(const ulonglong2*)(hb + j * DPP);  // (hk hk | hk1 hk1)
                fma2(aR[j], h.x, wr.x); fma2(aR[j], h.y, wr.y);
                fma2(aZ[j], h.x, wz.x); fma2(aZ[j], h.y, wz.y);
                fma2(aN[j], h.x, wn.x); fma2(aN[j], h.y, wn.y);
            }
        }
    }

    // epilogue: bias + coalesced STG.64
    {
        float2 b2;
        b2 = *(const float2*)(bih + c2);
#pragma unroll
        for (int j = 0; j < 8; ++j) {
            float2 p = unpk(aR[j]); p.x += b2.x; p.y += b2.y;
            *(float2*)(g_gi + (size_t)(row0 + r0 + j) * G3 + c2) = p;
        }
        b2 = *(const float2*)(bih + 128 + c2);
#pragma unroll
        for (int j = 0; j < 8; ++j) {
            float2 p = unpk(aZ[j]); p.x += b2.x; p.y += b2.y;
            *(float2*)(g_gi + (size_t)(row0 + r0 + j) * G3 + 128 + c2) = p;
        }
        b2 = *(const float2*)(bih + 256 + c2);
#pragma unroll
        for (int j = 0; j < 8; ++j) {
            float2 p = unpk(aN[j]); p.x += b2.x; p.y += b2.y;
            *(float2*)(g_gi + (size_t)(row0 + r0 + j) * G3 + 256 + c2) = p;
        }
    }
}

// ---------------------------------------------------------------------------
// GRU recurrent scan for one layer.
// 256 CTAs x 512 threads x 64 rows; all 20 steps on-chip. 16 warps = 4/SMSP.
// smem: Whh quad layout [64][WT2P] + ONE chunk-swapped dup h buffer [64][DPP]:
//   owners of h-cols [0,64) refill it at the end of each step (chunk0),
//   owners of [64,128) refill it between the two half-k loops (chunk1).
// Thread: 8 rows x 1 col-pair x 3 gates. Per k-pair: 3 wt LDS.128 + 8 h
// LDS.128 + 48 fma2 -> 320 wf/SM < 384 FMA cyc (fma-bound).
// ---------------------------------------------------------------------------
__global__ __launch_bounds__(512) void scan_kernel(
    const float* __restrict__ Whh, const float* __restrict__ bhh,
    float* __restrict__ hid)
{
    extern __shared__ float sm[];
    float* Wt2 = sm;                 // [64][WT2P]
    float* hB  = sm + 64 * WT2P;     // [64][DPP]  dup buffer (one 64-k chunk)

    int tid = threadIdx.x;
    fill_Wt2<HS, 512>(Wt2, Whh, tid);
    for (int i = tid; i < 64 * DPP; i += 512) hB[i] = 0.0f;   // chunk0 of h0 = 0

    int rg = tid >> 6;           // row-group 0..7 (8 rows each)
    int pp = tid & 63;           // column-pair 0..63 (h-cols c2, c2+1)
    int c2 = 2 * pp;
    int r0 = rg * 8;
    int m0 = blockIdx.x * 64;

    const float2 bR = *(const float2*)(bhh + c2);
    const float2 bZ = *(const float2*)(bhh + 128 + c2);
    const float2 bN = *(const float2*)(bhh + 256 + c2);

    float2 hreg[8];
#pragma unroll
    for (int j = 0; j < 8; ++j) hreg[j] = make_float2(0.0f, 0.0f);

    __syncthreads();

    for (int t = 0; t < Tt; ++t) {
        ULL aR[8], aZ[8], aN[8];
#pragma unroll
        for (int j = 0; j < 8; ++j) { aR[j] = 0ULL; aZ[j] = 0ULL; aN[j] = 0ULL; }

        // ---- chunk 0: k in [0,64), buffer holds dup h[0:64) ----
#pragma unroll 2
        for (int k2 = 0; k2 < 32; ++k2) {
            const float* wrow = Wt2 + (size_t)k2 * WT2P + 4 * pp;
            ulonglong2 wr = *(const ulonglong2*)(wrow);
            ulonglong2 wz = *(const ulonglong2*)(wrow + 256);
            ulonglong2 wn = *(const ulonglong2*)(wrow + 512);
            const float* hb = hB + r0 * DPP + 4 * k2;
#pragma unroll
            for (int j = 0; j < 8; ++j) {
                ulonglong2 h = *(const ulonglong2*)(hb + j * DPP);
                fma2(aR[j], h.x, wr.x); fma2(aR[j], h.y, wr.y);
                fma2(aZ[j], h.x, wz.x); fma2(aZ[j], h.y, wz.y);
                fma2(aN[j], h.x, wn.x); fma2(aN[j], h.y, wn.y);
            }
        }
        __syncthreads();   // B1: chunk0 reads done

        // owners of h-cols [64,128) write dup chunk1 into the buffer
        if (pp >= 32) {
            int off = 4 * pp - 128;          // float offset in row
#pragma unroll
            for (int j = 0; j < 8; ++j)
                *(float4*)(hB + (r0 + j) * DPP + off) =
                    make_float4(hreg[j].x, hreg[j].x, hreg[j].y, hreg[j].y);
        }
        __syncthreads();   // B2: chunk1 written

        // ---- chunk 1: k in [64,128) ----
#pragma unroll 2
        for (int k2 = 0; k2 < 32; ++k2) {
            const float* wrow = Wt2 + (size_t)(32 + k2) * WT2P + 4 * pp;
            ulonglong2 wr = *(const ulonglong2*)(wrow);
            ulonglong2 wz = *(const ulonglong2*)(wrow + 256);
            ulonglong2 wn = *(const ulonglong2*)(wrow + 512);
            const float* hb = hB + r0 * DPP + 4 * k2;
#pragma unroll
            for (int j = 0; j < 8; ++j) {
                ulonglong2 h = *(const ulonglong2*)(hb + j * DPP);
                fma2(aR[j], h.x, wr.x); fma2(aR[j], h.y, wr.y);
                fma2(aZ[j], h.x, wz.x); fma2(aZ[j], h.y, wz.y);
                fma2(aN[j], h.x, wn.x); fma2(aN[j], h.y, wn.y);
            }
        }
        __syncthreads();   // B3: chunk1 reads done

        // ---- gates + state update ----
#pragma unroll
        for (int j = 0; j < 8; ++j) {
            size_t rbase = (size_t)(m0 + r0 + j) * Tt + t;
            const float* gp = g_gi + rbase * G3;
            float2 giR = *(const float2*)(gp + c2);
            float2 giZ = *(const float2*)(gp + 128 + c2);
            float2 giN = *(const float2*)(gp + 256 + c2);
            float2 ghR = unpk(aR[j]), ghZ = unpk(aZ[j]), ghN = unpk(aN[j]);
            float rv0 = sigm(giR.x + ghR.x + bR.x);
            float rv1 = sigm(giR.y + ghR.y + bR.y);
            float zv0 = sigm(giZ.x + ghZ.x + bZ.x);
            float zv1 = sigm(giZ.y + ghZ.y + bZ.y);
            float nv0 = tanh_(giN.x + rv0 * (ghN.x + bN.x));
            float nv1 = tanh_(giN.y + rv1 * (ghN.y + bN.y));
            float hn0 = (1.0f - zv0) * nv0 + zv0 * hreg[j].x;
            float hn1 = (1.0f - zv1) * nv1 + zv1 * hreg[j].y;
            hreg[j] = make_float2(hn0, hn1);
            *(float2*)(g_ys + rbase * HS + c2) = hreg[j];
        }
        // owners of h-cols [0,64) write dup chunk0 for the next step
        if (pp < 32) {
            int off = 4 * pp;
#pragma unroll
            for (int j = 0; j < 8; ++j)
                *(float4*)(hB + (r0 + j) * DPP + off) =
                    make_float4(hreg[j].x, hreg[j].x, hreg[j].y, hreg[j].y);
        }
        __syncthreads();   // B4: chunk0 ready for next step
    }

    // hidden output: final h of rows with m % 8 == 7 -> row j == 7 in each group
    int b = (m0 + r0 + 7) >> 3;
    *(float2*)(hid + (size_t)b * HS + c2) = hreg[7];
}

// ---------------------------------------------------------------------------
// Output projection  out[m, e] = ys_last[m, :] @ out_W[e, :] + out_b[e]
// ---------------------------------------------------------------------------
__global__ __launch_bounds__(256) void out_kernel(
    const float* __restrict__ oW, const float* __restrict__ ob,
    float* __restrict__ out)
{
    __shared__ float sW[128 * 64];   // transposed [k][e]
    int tid = threadIdx.x;
    for (int idx = tid; idx < 64 * 128; idx += 256) {
        int e = idx >> 7, k = idx & 127;
        sW[k * 64 + e] = oW[idx];
    }
    __syncthreads();
    int gid = blockIdx.x * 256 + tid;       // gid = m*64 + e
    int e = gid & 63;
    int m = gid >> 6;
    const float* ys = g_ys + ((size_t)m * Tt + (Tt - 1)) * HS;
    float acc = ob[e];
#pragma unroll 8
    for (int k = 0; k < 128; ++k) acc = fmaf(ys[k], sW[k * 64 + e], acc);
    out[gid] = acc;
}

// ---------------------------------------------------------------------------
// Launch
// ---------------------------------------------------------------------------
extern "C" void kernel_launch(void* const* d_in, const int* in_sizes, int n_in,
                              void* d_out, int out_size) {
    const float* x    = (const float*)d_in[0];
    const float* pea  = (const float*)d_in[1];
    const float* pet  = (const float*)d_in[2];
    const float* embW = (const float*)d_in[3];
    const float* embB = (const float*)d_in[4];
    const float* Wih0 = (const float*)d_in[5];
    const float* WihR = (const float*)d_in[6];   // (2, 384, 128)
    const float* Whh  = (const float*)d_in[7];   // (3, 384, 128)
    const float* bih  = (const float*)d_in[8];   // (3, 384)
    const float* bhh  = (const float*)d_in[9];   // (3, 384)
    const float* outW = (const float*)d_in[10];  // (64, 128)
    const float* outB = (const float*)d_in[11];

    float* out = (float*)d_out;                  // [Mm*64]
    float* hid = out + OUT0;                     // [3][Bb][HS]

    const int smem64   = 32 * WT2P * 4 + 64 * DPP * 4;  //  99328 + 33792 = 133120
    const int smem128  = 64 * WT2P * 4 + 64 * DPP * 4;  // 198656 + 33792 = 232448
    const int smemScan = smem128;                       // 232448 (= 227 KB cap)
    cudaFuncSetAttribute(gi_gemm<64>,  cudaFuncAttributeMaxDynamicSharedMemorySize, smem64);
    cudaFuncSetAttribute(gi_gemm<128>, cudaFuncAttributeMaxDynamicSharedMemorySize, smem128);
    cudaFuncSetAttribute(scan_kernel,  cudaFuncAttributeMaxDynamicSharedMemorySize, smemScan);

    // layer 0 (embedding fused into the gi x-tile fill)
    gi_gemm<64><<<RT / 64, 512, smem64>>>(Wih0, bih, x, pea, pet, embW, embB);
    scan_kernel<<<Mm / 64, 512, smemScan>>>(Whh, bhh, hid);
    // layer 1
    gi_gemm<128><<<RT / 64, 512, smem128>>>(WihR, bih + G3, x, pea, pet, embW, embB);
    scan_kernel<<<Mm / 64, 512, smemScan>>>(Whh + (size_t)G3 * HS, bhh + G3,
                                            hid + (size_t)Bb * HS);
    // layer 2
    gi_gemm<128><<<RT / 64, 512, smem128>>>(WihR + (size_t)G3 * HS, bih + 2 * G3,
                                            x, pea, pet, embW, embB);
    scan_kernel<<<Mm / 64, 512, smemScan>>>(Whh + (size_t)2 * G3 * HS, bhh + 2 * G3,
                                            hid + (size_t)2 * Bb * HS);

    out_kernel<<<(Mm * 64) / 256, 256>>>(outW, outB, out);
}

// round 12
// speedup vs baseline: 1.3319x; 1.2672x over previous
#include <cuda_runtime.h>
#include <cuda_bf16.h>

constexpr int Bb  = 2048;
constexpr int Tt  = 20;
constexpr int Mm  = 16384;
constexpr int HS  = 128;
constexpr int G3  = 384;
constexpr int RT  = Mm * Tt;        // 327680
constexpr int WTP = 388;
constexpr int XP  = 128;
constexpr int HP  = 260;
constexpr int OUT0 = Mm * 64;

__device__ float g_gi[(size_t)RT * G3];
__device__ float g_ys[(size_t)RT * HS];

typedef unsigned long long ULL;

__device__ __forceinline__ void fma2(ULL& d, ULL a, ULL b) {
    asm("fma.rn.f32x2 %0, %1, %2, %0;" : "+l"(d) : "l"(a), "l"(b));
}
__device__ __forceinline__ float2 unpk(ULL v) {
    float2 f; asm("mov.b64 {%0, %1}, %2;" : "=f"(f.x), "=f"(f.y) : "l"(v)); return f;
}
__device__ __forceinline__ float sigm(float x) { return 1.0f / (1.0f + __expf(-x)); }
__device__ __forceinline__ float tanh_(float x) { return 1.0f - 2.0f / (__expf(2.0f * x) + 1.0f); }

__device__ __forceinline__ unsigned smem_u32(const void* p) {
    unsigned a;
    asm("{ .reg .u64 t; cvta.to.shared.u64 t, %1; cvt.u32.u64 %0, t; }" : "=r"(a) : "l"(p));
    return a;
}
__device__ __forceinline__ void ldsm4(unsigned* r, unsigned addr) {
    asm volatile("ldmatrix.sync.aligned.m8n8.x4.shared.b16 {%0,%1,%2,%3}, [%4];"
        : "=r"(r[0]), "=r"(r[1]), "=r"(r[2]), "=r"(r[3]) : "r"(addr));
}
__device__ __forceinline__ void mma16816(float* c, const unsigned* a, unsigned b0, unsigned b1) {
    asm volatile("mma.sync.aligned.m16n8k16.row.col.f32.bf16.bf16.f32 "
        "{%0,%1,%2,%3}, {%4,%5,%6,%7}, {%8,%9}, {%0,%1,%2,%3};"
        : "+f"(c[0]), "+f"(c[1]), "+f"(c[2]), "+f"(c[3])
        : "r"(a[0]), "r"(a[1]), "r"(a[2]), "r"(a[3]), "r"(b0), "r"(b1));
}

// split fp32 quad into hi/lo bf16 quads (packed as 8-byte values)
__device__ __forceinline__ void split4(float4 v, ULL& hi, ULL& lo) {
    float a[4] = {v.x, v.y, v.z, v.w};
    unsigned short hs[4], ls[4];
#pragma unroll
    for (int i = 0; i < 4; ++i) {
        __nv_bfloat16 h = __float2bfloat16(a[i]);
        hs[i] = ((__nv_bfloat16_raw)h).x;
        __nv_bfloat16 l = __float2bfloat16(a[i] - __bfloat162float(h));
        ls[i] = ((__nv_bfloat16_raw)l).x;
    }
    hi = (ULL)hs[0] | ((ULL)hs[1] << 16) | ((ULL)hs[2] << 32) | ((ULL)hs[3] << 48);
    lo = (ULL)ls[0] | ((ULL)ls[1] << 16) | ((ULL)ls[2] << 32) | ((ULL)ls[3] << 48);
}

// ---------------------------------------------------------------------------
// HMMA gi GEMM (layers 1,2): gi = ys @ Wih^T + bih via 2-term bf16 split.
// 2560 CTAs x 512 thr, 128 rows/CTA. Warp tile 32 rows x 48 gates.
// smem (bf16, pitch 136 elems = 272B -> ldmatrix conflict-free):
//   Ah@0 (128x136, 34816B) | Al@34816 | Bh@69632 (192x136, 52224B) | Bl@121856
// 2 gate-chunks of 192. Per k16-step/warp: 10 ldmatrix.x4 + 36 HMMA.
// ---------------------------------------------------------------------------
constexpr int PAB = 272;            // smem row pitch in bytes
constexpr int AH0 = 0, AL0 = 34816, BH0 = 69632, BL0 = 121856;
constexpr int SMEM_MMA = 174080;

__global__ __launch_bounds__(512) void gi_mma(
    const float* __restrict__ W, const float* __restrict__ bih)
{
    extern __shared__ char smc[];
    unsigned sb = smem_u32(smc);
    int tid = threadIdx.x, warp = tid >> 5, lane = tid & 31;
    size_t row0 = (size_t)blockIdx.x * 128;

    // fill A (hi/lo): 128 rows x 32 quads
    for (int idx = tid; idx < 128 * 32; idx += 512) {
        int r = idx >> 5, k4 = (idx & 31) * 4;
        float4 v = *(const float4*)(g_ys + (row0 + r) * HS + k4);
        ULL hi, lo; split4(v, hi, lo);
        int off = r * PAB + k4 * 2;
        *(ULL*)(smc + AH0 + off) = hi;
        *(ULL*)(smc + AL0 + off) = lo;
    }

    int m0  = (warp >> 2) * 32;      // warp row base
    int n0w = (warp & 3) * 48;       // warp gate base within chunk
    // ldmatrix lane address offsets (bytes)
    unsigned aoff = sb + (unsigned)((m0 + (lane & 7) + ((lane & 8) ? 8 : 0)) * PAB
                                    + ((lane & 16) ? 16 : 0));
    unsigned boff = sb + (unsigned)(BH0 + (n0w + (lane & 7) + ((lane & 8) ? 8 : 0)) * PAB
                                    + ((lane & 16) ? 16 : 0));

    for (int ch = 0; ch < 2; ++ch) {
        __syncthreads();   // A fill done (ch0) / previous chunk's B reads done
        // fill B chunk (hi/lo): 192 gates x 32 quads
        for (int idx = tid; idx < 192 * 32; idx += 512) {
            int gg = idx >> 5, k4 = (idx & 31) * 4;
            float4 v = *(const float4*)(W + (size_t)(ch * 192 + gg) * HS + k4);
            ULL hi, lo; split4(v, hi, lo);
            int off = gg * PAB + k4 * 2;
            *(ULL*)(smc + BH0 + off) = hi;
            *(ULL*)(smc + BL0 + off) = lo;
        }
        __syncthreads();

        float acc[2][6][4];
#pragma unroll
        for (int rt = 0; rt < 2; ++rt)
#pragma unroll
            for (int nt = 0; nt < 6; ++nt)
#pragma unroll
                for (int q = 0; q < 4; ++q) acc[rt][nt][q] = 0.0f;

        for (int ks = 0; ks < 8; ++ks) {
            unsigned ah0[4], al0[4], ah1[4], al1[4];
            unsigned ka = aoff + ks * 32;
            ldsm4(ah0, ka);
            ldsm4(al0, ka + AL0);
            ldsm4(ah1, ka + 16 * PAB);
            ldsm4(al1, ka + 16 * PAB + AL0);
#pragma unroll
            for (int p = 0; p < 3; ++p) {
                unsigned bh[4], bl[4];
                unsigned kb = boff + p * 16 * PAB + ks * 32;
                ldsm4(bh, kb);
                ldsm4(bl, kb + (BL0 - BH0));
                // even n-tile (2p): frag {r0, r2}; odd (2p+1): {r1, r3}
                mma16816(acc[0][2*p],   ah0, bh[0], bh[2]);
                mma16816(acc[0][2*p],   ah0, bl[0], bl[2]);
                mma16816(acc[0][2*p],   al0, bh[0], bh[2]);
                mma16816(acc[0][2*p+1], ah0, bh[1], bh[3]);
                mma16816(acc[0][2*p+1], ah0, bl[1], bl[3]);
                mma16816(acc[0][2*p+1], al0, bh[1], bh[3]);
                mma16816(acc[1][2*p],   ah1, bh[0], bh[2]);
                mma16816(acc[1][2*p],   ah1, bl[0], bl[2]);
                mma16816(acc[1][2*p],   al1, bh[0], bh[2]);
                mma16816(acc[1][2*p+1], ah1, bh[1], bh[3]);
                mma16816(acc[1][2*p+1], ah1, bl[1], bl[3]);
                mma16816(acc[1][2*p+1], al1, bh[1], bh[3]);
            }
        }

        // epilogue: c-frag (m = base + lane>>2 [+8], n = col0 + (lane&3)*2)
        int gb = ch * 192 + n0w;
        size_t rA = row0 + m0 + (lane >> 2);
#pragma unroll
        for (int rt = 0; rt < 2; ++rt) {
#pragma unroll
            for (int nt = 0; nt < 6; ++nt) {
                int col = gb + nt * 8 + (lane & 3) * 2;
                float2 bv = *(const float2*)(bih + col);
                float* p0 = g_gi + (rA + rt * 16) * G3 + col;
                *(float2*)p0 = make_float2(acc[rt][nt][0] + bv.x, acc[rt][nt][1] + bv.y);
                *(float2*)(p0 + 8 * G3) =
                    make_float2(acc[rt][nt][2] + bv.x, acc[rt][nt][3] + bv.y);
            }
        }
    }
}

// ---------------------------------------------------------------------------
// gi GEMM layer 0 (fused embedding), fp32 f32x2 path
// ---------------------------------------------------------------------------
__global__ __launch_bounds__(256) void gi_gemm64(
    const float* __restrict__ Wih, const float* __restrict__ bih,
    const float* __restrict__ x,   const float* __restrict__ pea,
    const float* __restrict__ pet, const float* __restrict__ embW,
    const float* __restrict__ embB)
{
    constexpr int K = 64;
    extern __shared__ float sm[];
    float* Wt = sm;                 // [64][WTP]
    float* xT = sm + K * WTP;       // [64][XP]

    int tid = threadIdx.x;
    for (int g = tid; g < G3; g += 256) {
        const float* src = Wih + (size_t)g * K;
#pragma unroll 4
        for (int k0 = 0; k0 < K; k0 += 4) {
            float4 w = *(const float4*)(src + k0);
            Wt[(k0 + 0) * WTP + g] = w.x;
            Wt[(k0 + 1) * WTP + g] = w.y;
            Wt[(k0 + 2) * WTP + g] = w.z;
            Wt[(k0 + 3) * WTP + g] = w.w;
        }
    }

    int warp = tid >> 5, l = tid & 31;
    int row0 = blockIdx.x * 64;

    ULL acc[3][8][2];
#pragma unroll
    for (int g = 0; g < 3; ++g)
#pragma unroll
        for (int j = 0; j < 8; ++j) { acc[g][j][0] = 0ULL; acc[g][j][1] = 0ULL; }

    __syncthreads();
    for (int idx = tid; idx < 64 * 16; idx += 256) {
        int r = idx >> 4, kq = idx & 15;
        int row = row0 + r;
        int t = row % Tt;
        int n = (row / Tt) & 7;
        float pe = __ldg(pet + t) + __ldg(pea + n);
        float2 xv = *(const float2*)(x + (size_t)row * 2);
        float x0 = xv.x + pe, x1 = xv.y + pe;
        float4 w0 = __ldg((const float4*)(embW + 8 * kq));
        float4 w1 = __ldg((const float4*)(embW + 8 * kq + 4));
        float4 b4 = __ldg((const float4*)(embB + 4 * kq));
        float4 v;
        v.x = fmaxf(fmaf(x0, w0.x, fmaf(x1, w0.y, b4.x)), 0.0f);
        v.y = fmaxf(fmaf(x0, w0.z, fmaf(x1, w0.w, b4.y)), 0.0f);
        v.z = fmaxf(fmaf(x0, w1.x, fmaf(x1, w1.y, b4.z)), 0.0f);
        v.w = fmaxf(fmaf(x0, w1.z, fmaf(x1, w1.w, b4.w)), 0.0f);
        float* d = xT + r * XP + 8 * kq;
        *(float4*)(d)     = make_float4(v.x, v.x, v.y, v.y);
        *(float4*)(d + 4) = make_float4(v.z, v.z, v.w, v.w);
    }
    __syncthreads();

#pragma unroll 4
    for (int k2 = 0; k2 < 32; ++k2) {
        const float* wb = Wt + (size_t)(2 * k2) * WTP + 4 * l;
        ulonglong2 wA0 = *(const ulonglong2*)(wb);
        ulonglong2 wA1 = *(const ulonglong2*)(wb + 128);
        ulonglong2 wA2 = *(const ulonglong2*)(wb + 256);
        ulonglong2 wB0 = *(const ulonglong2*)(wb + WTP);
        ulonglong2 wB1 = *(const ulonglong2*)(wb + WTP + 128);
        ulonglong2 wB2 = *(const ulonglong2*)(wb + WTP + 256);
        const float* hb = xT + (warp * 8) * XP + 4 * k2;
#pragma unroll
        for (int j = 0; j < 8; ++j) {
            ulonglong2 h = *(const ulonglong2*)(hb + j * XP);
            fma2(acc[0][j][0], h.x, wA0.x); fma2(acc[0][j][1], h.x, wA0.y);
            fma2(acc[1][j][0], h.x, wA1.x); fma2(acc[1][j][1], h.x, wA1.y);
            fma2(acc[2][j][0], h.x, wA2.x); fma2(acc[2][j][1], h.x, wA2.y);
            fma2(acc[0][j][0], h.y, wB0.x); fma2(acc[0][j][1], h.y, wB0.y);
            fma2(acc[1][j][0], h.y, wB1.x); fma2(acc[1][j][1], h.y, wB1.y);
            fma2(acc[2][j][0], h.y, wB2.x); fma2(acc[2][j][1], h.y, wB2.y);
        }
    }

#pragma unroll
    for (int g = 0; g < 3; ++g) {
        float4 b4 = __ldg((const float4*)(bih + g * 128 + 4 * l));
#pragma unroll
        for (int j = 0; j < 8; ++j) {
            float2 p0 = unpk(acc[g][j][0]);
            float2 p1 = unpk(acc[g][j][1]);
            float4 o = make_float4(p0.x + b4.x, p0.y + b4.y, p1.x + b4.z, p1.y + b4.w);
            *(float4*)(g_gi + (size_t)(row0 + warp * 8 + j) * G3 + g * 128 + 4 * l) = o;
        }
    }
}

// ---------------------------------------------------------------------------
// GRU scan (best-known: 512 CTAs x 256 thr x 32 rows)
// ---------------------------------------------------------------------------
__global__ __launch_bounds__(256) void scan_kernel(
    const float* __restrict__ Whh, const float* __restrict__ bhh,
    float* __restrict__ hid)
{
    extern __shared__ float sm[];
    float* Wt = sm;              // [128][WTP]
    float* hT = sm + HS * WTP;   // [32][HP]

    int tid = threadIdx.x;
    for (int g = tid; g < G3; g += 256) {
        const float* src = Whh + (size_t)g * HS;
#pragma unroll 4
        for (int k0 = 0; k0 < HS; k0 += 4) {
            float4 w = *(const float4*)(src + k0);
            Wt[(k0 + 0) * WTP + g] = w.x;
            Wt[(k0 + 1) * WTP + g] = w.y;
            Wt[(k0 + 2) * WTP + g] = w.z;
            Wt[(k0 + 3) * WTP + g] = w.w;
        }
    }
    for (int i = tid; i < 32 * HP; i += 256) hT[i] = 0.0f;

    int rg = tid >> 6;
    int pp = tid & 63;
    int c2 = 2 * pp;
    int r0 = rg * 8;
    int m0 = blockIdx.x * 32;

    const float2 bR = *(const float2*)(bhh + c2);
    const float2 bZ = *(const float2*)(bhh + 128 + c2);
    const float2 bN = *(const float2*)(bhh + 256 + c2);

    float2 hreg[8];
#pragma unroll
    for (int j = 0; j < 8; ++j) hreg[j] = make_float2(0.0f, 0.0f);

    __syncthreads();

    for (int t = 0; t < Tt; ++t) {
        float2 giR[8], giZ[8], giN[8];
#pragma unroll
        for (int j = 0; j < 8; ++j) {
            const float* gp = g_gi + ((size_t)(m0 + r0 + j) * Tt + t) * G3;
            giR[j] = *(const float2*)(gp + c2);
            giZ[j] = *(const float2*)(gp + 128 + c2);
            giN[j] = *(const float2*)(gp + 256 + c2);
        }

        ULL aR[8], aZ[8], aN[8];
#pragma unroll
        for (int j = 0; j < 8; ++j) { aR[j] = 0ULL; aZ[j] = 0ULL; aN[j] = 0ULL; }

#pragma unroll 4
        for (int k2 = 0; k2 < 64; ++k2) {
            const float* wb = Wt + (size_t)(2 * k2) * WTP + c2;
            ULL wr0 = *(const ULL*)(wb);
            ULL wz0 = *(const ULL*)(wb + 128);
            ULL wn0 = *(const ULL*)(wb + 256);
            ULL wr1 = *(const ULL*)(wb + WTP);
            ULL wz1 = *(const ULL*)(wb + WTP + 128);
            ULL wn1 = *(const ULL*)(wb + WTP + 256);
            const float* hb = hT + r0 * HP + 4 * k2;
#pragma unroll
            for (int j = 0; j < 8; ++j) {
                ulonglong2 h = *(const ulonglong2*)(hb + j * HP);
                fma2(aR[j], h.x, wr0); fma2(aZ[j], h.x, wz0); fma2(aN[j], h.x, wn0);
                fma2(aR[j], h.y, wr1); fma2(aZ[j], h.y, wz1); fma2(aN[j], h.y, wn1);
            }
        }
        __syncthreads();

#pragma unroll
        for (int j = 0; j < 8; ++j) {
            float2 ghR = unpk(aR[j]), ghZ = unpk(aZ[j]), ghN = unpk(aN[j]);
            float rv0 = sigm(giR[j].x + ghR.x + bR.x);
            float rv1 = sigm(giR[j].y + ghR.y + bR.y);
            float zv0 = sigm(giZ[j].x + ghZ.x + bZ.x);
            float zv1 = sigm(giZ[j].y + ghZ.y + bZ.y);
            float nv0 = tanh_(giN[j].x + rv0 * (ghN.x + bN.x));
            float nv1 = tanh_(giN[j].y + rv1 * (ghN.y + bN.y));
            float hn0 = (1.0f - zv0) * nv0 + zv0 * hreg[j].x;
            float hn1 = (1.0f - zv1) * nv1 + zv1 * hreg[j].y;
            hreg[j] = make_float2(hn0, hn1);
            *(float2*)(g_ys + ((size_t)(m0 + r0 + j) * Tt + t) * HS + c2) = hreg[j];
            *(float4*)(hT + (r0 + j) * HP + 4 * pp) = make_float4(hn0, hn0, hn1, hn1);
        }
        __syncthreads();
    }

    int b = (m0 + r0 + 7) >> 3;
    *(float2*)(hid + (size_t)b * HS + c2) = hreg[7];
}

// ---------------------------------------------------------------------------
__global__ __launch_bounds__(256) void out_kernel(
    const float* __restrict__ oW, const float* __restrict__ ob,
    float* __restrict__ out)
{
    __shared__ float sW[128 * 64];
    int tid = threadIdx.x;
    for (int idx = tid; idx < 64 * 128; idx += 256) {
        int e = idx >> 7, k = idx & 127;
        sW[k * 64 + e] = oW[idx];
    }
    __syncthreads();
    int gid = blockIdx.x * 256 + tid;
    int e = gid & 63;
    int m = gid >> 6;
    const float* ys = g_ys + ((size_t)m * Tt + (Tt - 1)) * HS;
    float acc = ob[e];
#pragma unroll 8
    for (int k = 0; k < 128; ++k) acc = fmaf(ys[k], sW[k * 64 + e], acc);
    out[gid] = acc;
}

// ---------------------------------------------------------------------------
extern "C" void kernel_launch(void* const* d_in, const int* in_sizes, int n_in,
                              void* d_out, int out_size) {
    const float* x    = (const float*)d_in[0];
    const float* pea  = (const float*)d_in[1];
    const float* pet  = (const float*)d_in[2];
    const float* embW = (const float*)d_in[3];
    const float* embB = (const float*)d_in[4];
    const float* Wih0 = (const float*)d_in[5];
    const float* WihR = (const float*)d_in[6];
    const float* Whh  = (const float*)d_in[7];
    const float* bih  = (const float*)d_in[8];
    const float* bhh  = (const float*)d_in[9];
    const float* outW = (const float*)d_in[10];
    const float* outB = (const float*)d_in[11];

    float* out = (float*)d_out;
    float* hid = out + OUT0;

    const int smem64   = 64 * WTP * 4 + 64 * XP * 4;   // 132096
    const int smemScan = 128 * WTP * 4 + 32 * HP * 4;  // 231936
    cudaFuncSetAttribute(gi_gemm64,   cudaFuncAttributeMaxDynamicSharedMemorySize, smem64);
    cudaFuncSetAttribute(scan_kernel, cudaFuncAttributeMaxDynamicSharedMemorySize, smemScan);
    cudaFuncSetAttribute(gi_mma,      cudaFuncAttributeMaxDynamicSharedMemorySize, SMEM_MMA);

    gi_gemm64<<<RT / 64, 256, smem64>>>(Wih0, bih, x, pea, pet, embW, embB);
    scan_kernel<<<Mm / 32, 256, smemScan>>>(Whh, bhh, hid);

    gi_mma<<<RT / 128, 512, SMEM_MMA>>>(WihR, bih + G3);
    scan_kernel<<<Mm / 32, 256, smemScan>>>(Whh + (size_t)G3 * HS, bhh + G3,
                                            hid + (size_t)Bb * HS);

    gi_mma<<<RT / 128, 512, SMEM_MMA>>>(WihR + (size_t)G3 * HS, bih + 2 * G3);
    scan_kernel<<<Mm / 32, 256, smemScan>>>(Whh + (size_t)2 * G3 * HS, bhh + 2 * G3,
                                            hid + (size_t)2 * Bb * HS);

    out_kernel<<<(Mm * 64) / 256, 256>>>(outW, outB, out);
}

// round 13
// speedup vs baseline: 1.6109x; 1.2094x over previous
#include <cuda_runtime.h>
#include <cuda_bf16.h>

constexpr int Bb  = 2048;
constexpr int Tt  = 20;
constexpr int Mm  = 16384;
constexpr int HS  = 128;
constexpr int G3  = 384;
constexpr int RT  = Mm * Tt;        // 327680
constexpr int WTP = 388;
constexpr int XP  = 128;
constexpr int OUT0 = Mm * 64;

__device__ float g_gi[(size_t)RT * G3];
__device__ float g_ys[(size_t)RT * HS];

typedef unsigned long long ULL;

__device__ __forceinline__ void fma2(ULL& d, ULL a, ULL b) {
    asm("fma.rn.f32x2 %0, %1, %2, %0;" : "+l"(d) : "l"(a), "l"(b));
}
__device__ __forceinline__ float2 unpk(ULL v) {
    float2 f; asm("mov.b64 {%0, %1}, %2;" : "=f"(f.x), "=f"(f.y) : "l"(v)); return f;
}
__device__ __forceinline__ float sigm(float x) { return 1.0f / (1.0f + __expf(-x)); }
__device__ __forceinline__ float tanh_(float x) { return 1.0f - 2.0f / (__expf(2.0f * x) + 1.0f); }

__device__ __forceinline__ unsigned smem_u32(const void* p) {
    unsigned a;
    asm("{ .reg .u64 t; cvta.to.shared.u64 t, %1; cvt.u32.u64 %0, t; }" : "=r"(a) : "l"(p));
    return a;
}
__device__ __forceinline__ void ldsm4(unsigned* r, unsigned addr) {
    asm volatile("ldmatrix.sync.aligned.m8n8.x4.shared.b16 {%0,%1,%2,%3}, [%4];"
        : "=r"(r[0]), "=r"(r[1]), "=r"(r[2]), "=r"(r[3]) : "r"(addr));
}
__device__ __forceinline__ void mma16816(float* c, const unsigned* a, unsigned b0, unsigned b1) {
    asm volatile("mma.sync.aligned.m16n8k16.row.col.f32.bf16.bf16.f32 "
        "{%0,%1,%2,%3}, {%4,%5,%6,%7}, {%8,%9}, {%0,%1,%2,%3};"
        : "+f"(c[0]), "+f"(c[1]), "+f"(c[2]), "+f"(c[3])
        : "r"(a[0]), "r"(a[1]), "r"(a[2]), "r"(a[3]), "r"(b0), "r"(b1));
}

// split fp32 quad into hi/lo bf16 quads (packed as 8-byte values)
__device__ __forceinline__ void split4(float4 v, ULL& hi, ULL& lo) {
    float a[4] = {v.x, v.y, v.z, v.w};
    unsigned short hs[4], ls[4];
#pragma unroll
    for (int i = 0; i < 4; ++i) {
        __nv_bfloat16 h = __float2bfloat16(a[i]);
        hs[i] = ((__nv_bfloat16_raw)h).x;
        __nv_bfloat16 l = __float2bfloat16(a[i] - __bfloat162float(h));
        ls[i] = ((__nv_bfloat16_raw)l).x;
    }
    hi = (ULL)hs[0] | ((ULL)hs[1] << 16) | ((ULL)hs[2] << 32) | ((ULL)hs[3] << 48);
    lo = (ULL)ls[0] | ((ULL)ls[1] << 16) | ((ULL)ls[2] << 32) | ((ULL)ls[3] << 48);
}
__device__ __forceinline__ unsigned split1(float x, unsigned short& lo) {
    __nv_bfloat16 h = __float2bfloat16(x);
    lo = ((__nv_bfloat16_raw)__float2bfloat16(x - __bfloat162float(h))).x;
    return ((__nv_bfloat16_raw)h).x;
}

// ---------------------------------------------------------------------------
// HMMA gi GEMM (layers 1,2): gi = ys @ Wih^T + bih via 2-term bf16 split.
// (verified R12 kernel, unchanged)
// ---------------------------------------------------------------------------
constexpr int PAB = 272;            // smem row pitch in bytes
constexpr int AH0 = 0, AL0 = 34816, BH0 = 69632, BL0 = 121856;
constexpr int SMEM_MMA = 174080;

__global__ __launch_bounds__(512) void gi_mma(
    const float* __restrict__ W, const float* __restrict__ bih)
{
    extern __shared__ char smc[];
    unsigned sb = smem_u32(smc);
    int tid = threadIdx.x, warp = tid >> 5, lane = tid & 31;
    size_t row0 = (size_t)blockIdx.x * 128;

    for (int idx = tid; idx < 128 * 32; idx += 512) {
        int r = idx >> 5, k4 = (idx & 31) * 4;
        float4 v = *(const float4*)(g_ys + (row0 + r) * HS + k4);
        ULL hi, lo; split4(v, hi, lo);
        int off = r * PAB + k4 * 2;
        *(ULL*)(smc + AH0 + off) = hi;
        *(ULL*)(smc + AL0 + off) = lo;
    }

    int m0  = (warp >> 2) * 32;
    int n0w = (warp & 3) * 48;
    unsigned aoff = sb + (unsigned)((m0 + (lane & 7) + ((lane & 8) ? 8 : 0)) * PAB
                                    + ((lane & 16) ? 16 : 0));
    unsigned boff = sb + (unsigned)(BH0 + (n0w + (lane & 7) + ((lane & 8) ? 8 : 0)) * PAB
                                    + ((lane & 16) ? 16 : 0));

    for (int ch = 0; ch < 2; ++ch) {
        __syncthreads();
        for (int idx = tid; idx < 192 * 32; idx += 512) {
            int gg = idx >> 5, k4 = (idx & 31) * 4;
            float4 v = *(const float4*)(W + (size_t)(ch * 192 + gg) * HS + k4);
            ULL hi, lo; split4(v, hi, lo);
            int off = gg * PAB + k4 * 2;
            *(ULL*)(smc + BH0 + off) = hi;
            *(ULL*)(smc + BL0 + off) = lo;
        }
        __syncthreads();

        float acc[2][6][4];
#pragma unroll
        for (int rt = 0; rt < 2; ++rt)
#pragma unroll
            for (int nt = 0; nt < 6; ++nt)
#pragma unroll
                for (int q = 0; q < 4; ++q) acc[rt][nt][q] = 0.0f;

        for (int ks = 0; ks < 8; ++ks) {
            unsigned ah0[4], al0[4], ah1[4], al1[4];
            unsigned ka = aoff + ks * 32;
            ldsm4(ah0, ka);
            ldsm4(al0, ka + AL0);
            ldsm4(ah1, ka + 16 * PAB);
            ldsm4(al1, ka + 16 * PAB + AL0);
#pragma unroll
            for (int p = 0; p < 3; ++p) {
                unsigned bh[4], bl[4];
                unsigned kb = boff + p * 16 * PAB + ks * 32;
                ldsm4(bh, kb);
                ldsm4(bl, kb + (BL0 - BH0));
                mma16816(acc[0][2*p],   ah0, bh[0], bh[2]);
                mma16816(acc[0][2*p],   ah0, bl[0], bl[2]);
                mma16816(acc[0][2*p],   al0, bh[0], bh[2]);
                mma16816(acc[0][2*p+1], ah0, bh[1], bh[3]);
                mma16816(acc[0][2*p+1], ah0, bl[1], bl[3]);
                mma16816(acc[0][2*p+1], al0, bh[1], bh[3]);
                mma16816(acc[1][2*p],   ah1, bh[0], bh[2]);
                mma16816(acc[1][2*p],   ah1, bl[0], bl[2]);
                mma16816(acc[1][2*p],   al1, bh[0], bh[2]);
                mma16816(acc[1][2*p+1], ah1, bh[1], bh[3]);
                mma16816(acc[1][2*p+1], ah1, bl[1], bl[3]);
                mma16816(acc[1][2*p+1], al1, bh[1], bh[3]);
            }
        }

        int gb = ch * 192 + n0w;
        size_t rA = row0 + m0 + (lane >> 2);
#pragma unroll
        for (int rt = 0; rt < 2; ++rt) {
#pragma unroll
            for (int nt = 0; nt < 6; ++nt) {
                int col = gb + nt * 8 + (lane & 3) * 2;
                float2 bv = *(const float2*)(bih + col);
                float* p0 = g_gi + (rA + rt * 16) * G3 + col;
                *(float2*)p0 = make_float2(acc[rt][nt][0] + bv.x, acc[rt][nt][1] + bv.y);
                *(float2*)(p0 + 8 * G3) =
                    make_float2(acc[rt][nt][2] + bv.x, acc[rt][nt][3] + bv.y);
            }
        }
    }
}

// ---------------------------------------------------------------------------
// HMMA GRU scan: 512 CTAs x 256 thr x 32 rows; gh via bf16-split mma.
// smem: Whh_hi [384][136]bf16 @0 | Whh_lo @104448 | h_hi [32][136] @208896 |
//       h_lo @217600  (total 226304 B)
// Warp w owns gate cols {w*16.., 128+w*16.., 256+w*16..}: full r/z/n triplet
// for its h-columns -> register-local state update, 2 barriers/step.
// ---------------------------------------------------------------------------
constexpr int WH0 = 0, WL0 = 104448, HH0 = 208896;
constexpr int SMEM_SCM = 226304;

__global__ __launch_bounds__(256) void scan_mma(
    const float* __restrict__ Whh, const float* __restrict__ bhh,
    float* __restrict__ hid)
{
    extern __shared__ char smc[];
    unsigned sb = smem_u32(smc);
    int tid = threadIdx.x, warp = tid >> 5, lane = tid & 31;
    int m0 = blockIdx.x * 32;

    // Whh split fill: 384 gates x 32 quads
    for (int idx = tid; idx < 384 * 32; idx += 256) {
        int g = idx >> 5, k4 = (idx & 31) * 4;
        float4 v = *(const float4*)(Whh + (size_t)g * HS + k4);
        ULL hi, lo; split4(v, hi, lo);
        int off = g * PAB + k4 * 2;
        *(ULL*)(smc + WH0 + off) = hi;
        *(ULL*)(smc + WL0 + off) = lo;
    }
    // h = 0 (both hi and lo regions: 17408 B)
    for (int i = tid; i < 4352; i += 256) ((unsigned*)(smc + HH0))[i] = 0u;

    int lr   = (lane & 7) + ((lane & 8) ? 8 : 0);
    int lo16 = (lane & 16) ? 16 : 0;
    unsigned abase = sb + (unsigned)(HH0 + lr * PAB + lo16);
    unsigned bbase = sb + (unsigned)(WH0 + (warp * 16 + lr) * PAB + lo16);

    int cq = (lane & 3) * 2;
    int rq = lane >> 2;

    float2 biR[2], biZ[2], biN[2];
#pragma unroll
    for (int nt = 0; nt < 2; ++nt) {
        int c = warp * 16 + nt * 8 + cq;
        biR[nt] = *(const float2*)(bhh + c);
        biZ[nt] = *(const float2*)(bhh + 128 + c);
        biN[nt] = *(const float2*)(bhh + 256 + c);
    }

    float2 hreg[2][2][2];   // [mt][rh][nt]
#pragma unroll
    for (int a = 0; a < 2; ++a)
#pragma unroll
        for (int b = 0; b < 2; ++b)
#pragma unroll
            for (int c = 0; c < 2; ++c) hreg[a][b][c] = make_float2(0.0f, 0.0f);

    __syncthreads();

    for (int t = 0; t < Tt; ++t) {
        float acc[2][3][2][4];   // [mt][slice rzn][nt][frag]
#pragma unroll
        for (int a = 0; a < 2; ++a)
#pragma unroll
            for (int s = 0; s < 3; ++s)
#pragma unroll
                for (int n = 0; n < 2; ++n)
#pragma unroll
                    for (int q = 0; q < 4; ++q) acc[a][s][n][q] = 0.0f;

        for (int ks = 0; ks < 8; ++ks) {
            unsigned ka = abase + ks * 32;
            unsigned ah0[4], al0[4], ah1[4], al1[4];
            ldsm4(ah0, ka);
            ldsm4(al0, ka + 8704);
            ldsm4(ah1, ka + 16 * PAB);
            ldsm4(al1, ka + 16 * PAB + 8704);
#pragma unroll
            for (int s = 0; s < 3; ++s) {
                unsigned kb = bbase + (unsigned)(s * 128 * PAB) + ks * 32;
                unsigned bh[4], bl[4];
                ldsm4(bh, kb);
                ldsm4(bl, kb + (unsigned)WL0);
                mma16816(acc[0][s][0], ah0, bh[0], bh[2]);
                mma16816(acc[0][s][0], ah0, bl[0], bl[2]);
                mma16816(acc[0][s][0], al0, bh[0], bh[2]);
                mma16816(acc[0][s][1], ah0, bh[1], bh[3]);
                mma16816(acc[0][s][1], ah0, bl[1], bl[3]);
                mma16816(acc[0][s][1], al0, bh[1], bh[3]);
                mma16816(acc[1][s][0], ah1, bh[0], bh[2]);
                mma16816(acc[1][s][0], ah1, bl[0], bl[2]);
                mma16816(acc[1][s][0], al1, bh[0], bh[2]);
                mma16816(acc[1][s][1], ah1, bh[1], bh[3]);
                mma16816(acc[1][s][1], ah1, bl[1], bl[3]);
                mma16816(acc[1][s][1], al1, bh[1], bh[3]);
            }
        }
        __syncthreads();   // all h reads of this step done

#pragma unroll
        for (int mt = 0; mt < 2; ++mt)
#pragma unroll
        for (int rh = 0; rh < 2; ++rh)
#pragma unroll
        for (int nt = 0; nt < 2; ++nt) {
            int m = mt * 16 + rh * 8 + rq;
            int c = warp * 16 + nt * 8 + cq;
            size_t rbase = (size_t)(m0 + m) * Tt + t;
            const float* gp = g_gi + rbase * G3;
            float2 giR = *(const float2*)(gp + c);
            float2 giZ = *(const float2*)(gp + 128 + c);
            float2 giN = *(const float2*)(gp + 256 + c);
            float ghR0 = acc[mt][0][nt][rh*2], ghR1 = acc[mt][0][nt][rh*2+1];
            float ghZ0 = acc[mt][1][nt][rh*2], ghZ1 = acc[mt][1][nt][rh*2+1];
            float ghN0 = acc[mt][2][nt][rh*2], ghN1 = acc[mt][2][nt][rh*2+1];
            float rv0 = sigm(giR.x + ghR0 + biR[nt].x);
            float rv1 = sigm(giR.y + ghR1 + biR[nt].y);
            float zv0 = sigm(giZ.x + ghZ0 + biZ[nt].x);
            float zv1 = sigm(giZ.y + ghZ1 + biZ[nt].y);
            float nv0 = tanh_(giN.x + rv0 * (ghN0 + biN[nt].x));
            float nv1 = tanh_(giN.y + rv1 * (ghN1 + biN[nt].y));
            float hn0 = (1.0f - zv0) * nv0 + zv0 * hreg[mt][rh][nt].x;
            float hn1 = (1.0f - zv1) * nv1 + zv1 * hreg[mt][rh][nt].y;
            hreg[mt][rh][nt] = make_float2(hn0, hn1);
            *(float2*)(g_ys + rbase * HS + c) = hreg[mt][rh][nt];
            unsigned short l0, l1;
            unsigned short h0 = split1(hn0, l0);
            unsigned short h1 = split1(hn1, l1);
            int off = m * PAB + c * 2;
            *(unsigned*)(smc + HH0 + off)        = (unsigned)h0 | ((unsigned)h1 << 16);
            *(unsigned*)(smc + HH0 + 8704 + off) = (unsigned)l0 | ((unsigned)l1 << 16);
        }
        __syncthreads();   // h_new visible for next step
    }

    // hidden output: rows m%8==7 -> rq==7 threads own them
    if (rq == 7) {
#pragma unroll
        for (int mt = 0; mt < 2; ++mt)
#pragma unroll
        for (int rh = 0; rh < 2; ++rh)
#pragma unroll
        for (int nt = 0; nt < 2; ++nt) {
            int m = mt * 16 + rh * 8 + 7;
            int b = (m0 + m) >> 3;
            int c = warp * 16 + nt * 8 + cq;
            *(float2*)(hid + (size_t)b * HS + c) = hreg[mt][rh][nt];
        }
    }
}

// ---------------------------------------------------------------------------
// gi GEMM layer 0 (fused embedding), fp32 f32x2 path (verified)
// ---------------------------------------------------------------------------
__global__ __launch_bounds__(256) void gi_gemm64(
    const float* __restrict__ Wih, const float* __restrict__ bih,
    const float* __restrict__ x,   const float* __restrict__ pea,
    const float* __restrict__ pet, const float* __restrict__ embW,
    const float* __restrict__ embB)
{
    constexpr int K = 64;
    extern __shared__ float sm[];
    float* Wt = sm;
    float* xT = sm + K * WTP;

    int tid = threadIdx.x;
    for (int g = tid; g < G3; g += 256) {
        const float* src = Wih + (size_t)g * K;
#pragma unroll 4
        for (int k0 = 0; k0 < K; k0 += 4) {
            float4 w = *(const float4*)(src + k0);
            Wt[(k0 + 0) * WTP + g] = w.x;
            Wt[(k0 + 1) * WTP + g] = w.y;
            Wt[(k0 + 2) * WTP + g] = w.z;
            Wt[(k0 + 3) * WTP + g] = w.w;
        }
    }

    int warp = tid >> 5, l = tid & 31;
    int row0 = blockIdx.x * 64;

    ULL acc[3][8][2];
#pragma unroll
    for (int g = 0; g < 3; ++g)
#pragma unroll
        for (int j = 0; j < 8; ++j) { acc[g][j][0] = 0ULL; acc[g][j][1] = 0ULL; }

    __syncthreads();
    for (int idx = tid; idx < 64 * 16; idx += 256) {
        int r = idx >> 4, kq = idx & 15;
        int row = row0 + r;
        int t = row % Tt;
        int n = (row / Tt) & 7;
        float pe = __ldg(pet + t) + __ldg(pea + n);
        float2 xv = *(const float2*)(x + (size_t)row * 2);
        float x0 = xv.x + pe, x1 = xv.y + pe;
        float4 w0 = __ldg((const float4*)(embW + 8 * kq));
        float4 w1 = __ldg((const float4*)(embW + 8 * kq + 4));
        float4 b4 = __ldg((const float4*)(embB + 4 * kq));
        float4 v;
        v.x = fmaxf(fmaf(x0, w0.x, fmaf(x1, w0.y, b4.x)), 0.0f);
        v.y = fmaxf(fmaf(x0, w0.z, fmaf(x1, w0.w, b4.y)), 0.0f);
        v.z = fmaxf(fmaf(x0, w1.x, fmaf(x1, w1.y, b4.z)), 0.0f);
        v.w = fmaxf(fmaf(x0, w1.z, fmaf(x1, w1.w, b4.w)), 0.0f);
        float* d = xT + r * XP + 8 * kq;
        *(float4*)(d)     = make_float4(v.x, v.x, v.y, v.y);
        *(float4*)(d + 4) = make_float4(v.z, v.z, v.w, v.w);
    }
    __syncthreads();

#pragma unroll 4
    for (int k2 = 0; k2 < 32; ++k2) {
        const float* wb = Wt + (size_t)(2 * k2) * WTP + 4 * l;
        ulonglong2 wA0 = *(const ulonglong2*)(wb);
        ulonglong2 wA1 = *(const ulonglong2*)(wb + 128);
        ulonglong2 wA2 = *(const ulonglong2*)(wb + 256);
        ulonglong2 wB0 = *(const ulonglong2*)(wb + WTP);
        ulonglong2 wB1 = *(const ulonglong2*)(wb + WTP + 128);
        ulonglong2 wB2 = *(const ulonglong2*)(wb + WTP + 256);
        const float* hb = xT + (warp * 8) * XP + 4 * k2;
#pragma unroll
        for (int j = 0; j < 8; ++j) {
            ulonglong2 h = *(const ulonglong2*)(hb + j * XP);
            fma2(acc[0][j][0], h.x, wA0.x); fma2(acc[0][j][1], h.x, wA0.y);
            fma2(acc[1][j][0], h.x, wA1.x); fma2(acc[1][j][1], h.x, wA1.y);
            fma2(acc[2][j][0], h.x, wA2.x); fma2(acc[2][j][1], h.x, wA2.y);
            fma2(acc[0][j][0], h.y, wB0.x); fma2(acc[0][j][1], h.y, wB0.y);
            fma2(acc[1][j][0], h.y, wB1.x); fma2(acc[1][j][1], h.y, wB1.y);
            fma2(acc[2][j][0], h.y, wB2.x); fma2(acc[2][j][1], h.y, wB2.y);
        }
    }

#pragma unroll
    for (int g = 0; g < 3; ++g) {
        float4 b4 = __ldg((const float4*)(bih + g * 128 + 4 * l));
#pragma unroll
        for (int j = 0; j < 8; ++j) {
            float2 p0 = unpk(acc[g][j][0]);
            float2 p1 = unpk(acc[g][j][1]);
            float4 o = make_float4(p0.x + b4.x, p0.y + b4.y, p1.x + b4.z, p1.y + b4.w);
            *(float4*)(g_gi + (size_t)(row0 + warp * 8 + j) * G3 + g * 128 + 4 * l) = o;
        }
    }
}

// ---------------------------------------------------------------------------
__global__ __launch_bounds__(256) void out_kernel(
    const float* __restrict__ oW, const float* __restrict__ ob,
    float* __restrict__ out)
{
    __shared__ float sW[128 * 64];
    int tid = threadIdx.x;
    for (int idx = tid; idx < 64 * 128; idx += 256) {
        int e = idx >> 7, k = idx & 127;
        sW[k * 64 + e] = oW[idx];
    }
    __syncthreads();
    int gid = blockIdx.x * 256 + tid;
    int e = gid & 63;
    int m = gid >> 6;
    const float* ys = g_ys + ((size_t)m * Tt + (Tt - 1)) * HS;
    float acc = ob[e];
#pragma unroll 8
    for (int k = 0; k < 128; ++k) acc = fmaf(ys[k], sW[k * 64 + e], acc);
    out[gid] = acc;
}

// ---------------------------------------------------------------------------
extern "C" void kernel_launch(void* const* d_in, const int* in_sizes, int n_in,
                              void* d_out, int out_size) {
    const float* x    = (const float*)d_in[0];
    const float* pea  = (const float*)d_in[1];
    const float* pet  = (const float*)d_in[2];
    const float* embW = (const float*)d_in[3];
    const float* embB = (const float*)d_in[4];
    const float* Wih0 = (const float*)d_in[5];
    const float* WihR = (const float*)d_in[6];
    const float* Whh  = (const float*)d_in[7];
    const float* bih  = (const float*)d_in[8];
    const float* bhh  = (const float*)d_in[9];
    const float* outW = (const float*)d_in[10];
    const float* outB = (const float*)d_in[11];

    float* out = (float*)d_out;
    float* hid = out + OUT0;

    const int smem64 = 64 * WTP * 4 + 64 * XP * 4;   // 132096
    cudaFuncSetAttribute(gi_gemm64, cudaFuncAttributeMaxDynamicSharedMemorySize, smem64);
    cudaFuncSetAttribute(gi_mma,    cudaFuncAttributeMaxDynamicSharedMemorySize, SMEM_MMA);
    cudaFuncSetAttribute(scan_mma,  cudaFuncAttributeMaxDynamicSharedMemorySize, SMEM_SCM);

    gi_gemm64<<<RT / 64, 256, smem64>>>(Wih0, bih, x, pea, pet, embW, embB);
    scan_mma<<<Mm / 32, 256, SMEM_SCM>>>(Whh, bhh, hid);

    gi_mma<<<RT / 128, 512, SMEM_MMA>>>(WihR, bih + G3);
    scan_mma<<<Mm / 32, 256, SMEM_SCM>>>(Whh + (size_t)G3 * HS, bhh + G3,
                                         hid + (size_t)Bb * HS);

    gi_mma<<<RT / 128, 512, SMEM_MMA>>>(WihR + (size_t)G3 * HS, bih + 2 * G3);
    scan_mma<<<Mm / 32, 256, SMEM_SCM>>>(Whh + (size_t)2 * G3 * HS, bhh + 2 * G3,
                                         hid + (size_t)2 * Bb * HS);

    out_kernel<<<(Mm * 64) / 256, 256>>>(outW, outB, out);
}

// round 14
// speedup vs baseline: 2.0385x; 1.2655x over previous
#include <cuda_runtime.h>
#include <cuda_bf16.h>

constexpr int Bb  = 2048;
constexpr int Tt  = 20;
constexpr int Mm  = 16384;
constexpr int HS  = 128;
constexpr int G3  = 384;
constexpr int RT  = Mm * Tt;        // 327680
constexpr int WTP = 388;
constexpr int XP  = 128;
constexpr int OUT0 = Mm * 64;

__device__ float g_gi[(size_t)RT * G3];
__device__ float g_ys[(size_t)RT * HS];

typedef unsigned long long ULL;

__device__ __forceinline__ void fma2(ULL& d, ULL a, ULL b) {
    asm("fma.rn.f32x2 %0, %1, %2, %0;" : "+l"(d) : "l"(a), "l"(b));
}
__device__ __forceinline__ float2 unpk(ULL v) {
    float2 f; asm("mov.b64 {%0, %1}, %2;" : "=f"(f.x), "=f"(f.y) : "l"(v)); return f;
}
__device__ __forceinline__ float sigm(float x) { return 1.0f / (1.0f + __expf(-x)); }
__device__ __forceinline__ float tanh_(float x) { return 1.0f - 2.0f / (__expf(2.0f * x) + 1.0f); }

__device__ __forceinline__ unsigned smem_u32(const void* p) {
    unsigned a;
    asm("{ .reg .u64 t; cvta.to.shared.u64 t, %1; cvt.u32.u64 %0, t; }" : "=r"(a) : "l"(p));
    return a;
}
__device__ __forceinline__ void ldsm4(unsigned* r, unsigned addr) {
    asm volatile("ldmatrix.sync.aligned.m8n8.x4.shared.b16 {%0,%1,%2,%3}, [%4];"
        : "=r"(r[0]), "=r"(r[1]), "=r"(r[2]), "=r"(r[3]) : "r"(addr));
}
__device__ __forceinline__ void mma16816(float* c, const unsigned* a, unsigned b0, unsigned b1) {
    asm volatile("mma.sync.aligned.m16n8k16.row.col.f32.bf16.bf16.f32 "
        "{%0,%1,%2,%3}, {%4,%5,%6,%7}, {%8,%9}, {%0,%1,%2,%3};"
        : "+f"(c[0]), "+f"(c[1]), "+f"(c[2]), "+f"(c[3])
        : "r"(a[0]), "r"(a[1]), "r"(a[2]), "r"(a[3]), "r"(b0), "r"(b1));
}

__device__ __forceinline__ void split4(float4 v, ULL& hi, ULL& lo) {
    float a[4] = {v.x, v.y, v.z, v.w};
    unsigned short hs[4], ls[4];
#pragma unroll
    for (int i = 0; i < 4; ++i) {
        __nv_bfloat16 h = __float2bfloat16(a[i]);
        hs[i] = ((__nv_bfloat16_raw)h).x;
        __nv_bfloat16 l = __float2bfloat16(a[i] - __bfloat162float(h));
        ls[i] = ((__nv_bfloat16_raw)l).x;
    }
    hi = (ULL)hs[0] | ((ULL)hs[1] << 16) | ((ULL)hs[2] << 32) | ((ULL)hs[3] << 48);
    lo = (ULL)ls[0] | ((ULL)ls[1] << 16) | ((ULL)ls[2] << 32) | ((ULL)ls[3] << 48);
}
__device__ __forceinline__ unsigned split1(float x, unsigned short& lo) {
    __nv_bfloat16 h = __float2bfloat16(x);
    lo = ((__nv_bfloat16_raw)__float2bfloat16(x - __bfloat162float(h))).x;
    return ((__nv_bfloat16_raw)h).x;
}

// ---------------------------------------------------------------------------
// HMMA gi GEMM (layers 1,2) — verified R12/R13 kernel, unchanged.
// ---------------------------------------------------------------------------
constexpr int PAB = 272;
constexpr int AH0 = 0, AL0 = 34816, BH0 = 69632, BL0 = 121856;
constexpr int SMEM_MMA = 174080;

__global__ __launch_bounds__(512) void gi_mma(
    const float* __restrict__ W, const float* __restrict__ bih)
{
    extern __shared__ char smc[];
    unsigned sb = smem_u32(smc);
    int tid = threadIdx.x, warp = tid >> 5, lane = tid & 31;
    size_t row0 = (size_t)blockIdx.x * 128;

    for (int idx = tid; idx < 128 * 32; idx += 512) {
        int r = idx >> 5, k4 = (idx & 31) * 4;
        float4 v = *(const float4*)(g_ys + (row0 + r) * HS + k4);
        ULL hi, lo; split4(v, hi, lo);
        int off = r * PAB + k4 * 2;
        *(ULL*)(smc + AH0 + off) = hi;
        *(ULL*)(smc + AL0 + off) = lo;
    }

    int m0  = (warp >> 2) * 32;
    int n0w = (warp & 3) * 48;
    unsigned aoff = sb + (unsigned)((m0 + (lane & 7) + ((lane & 8) ? 8 : 0)) * PAB
                                    + ((lane & 16) ? 16 : 0));
    unsigned boff = sb + (unsigned)(BH0 + (n0w + (lane & 7) + ((lane & 8) ? 8 : 0)) * PAB
                                    + ((lane & 16) ? 16 : 0));

    for (int ch = 0; ch < 2; ++ch) {
        __syncthreads();
        for (int idx = tid; idx < 192 * 32; idx += 512) {
            int gg = idx >> 5, k4 = (idx & 31) * 4;
            float4 v = *(const float4*)(W + (size_t)(ch * 192 + gg) * HS + k4);
            ULL hi, lo; split4(v, hi, lo);
            int off = gg * PAB + k4 * 2;
            *(ULL*)(smc + BH0 + off) = hi;
            *(ULL*)(smc + BL0 + off) = lo;
        }
        __syncthreads();

        float acc[2][6][4];
#pragma unroll
        for (int rt = 0; rt < 2; ++rt)
#pragma unroll
            for (int nt = 0; nt < 6; ++nt)
#pragma unroll
                for (int q = 0; q < 4; ++q) acc[rt][nt][q] = 0.0f;

        for (int ks = 0; ks < 8; ++ks) {
            unsigned ah0[4], al0[4], ah1[4], al1[4];
            unsigned ka = aoff + ks * 32;
            ldsm4(ah0, ka);
            ldsm4(al0, ka + AL0);
            ldsm4(ah1, ka + 16 * PAB);
            ldsm4(al1, ka + 16 * PAB + AL0);
#pragma unroll
            for (int p = 0; p < 3; ++p) {
                unsigned bh[4], bl[4];
                unsigned kb = boff + p * 16 * PAB + ks * 32;
                ldsm4(bh, kb);
                ldsm4(bl, kb + (BL0 - BH0));
                mma16816(acc[0][2*p],   ah0, bh[0], bh[2]);
                mma16816(acc[0][2*p],   ah0, bl[0], bl[2]);
                mma16816(acc[0][2*p],   al0, bh[0], bh[2]);
                mma16816(acc[0][2*p+1], ah0, bh[1], bh[3]);
                mma16816(acc[0][2*p+1], ah0, bl[1], bl[3]);
                mma16816(acc[0][2*p+1], al0, bh[1], bh[3]);
                mma16816(acc[1][2*p],   ah1, bh[0], bh[2]);
                mma16816(acc[1][2*p],   ah1, bl[0], bl[2]);
                mma16816(acc[1][2*p],   al1, bh[0], bh[2]);
                mma16816(acc[1][2*p+1], ah1, bh[1], bh[3]);
                mma16816(acc[1][2*p+1], ah1, bl[1], bl[3]);
                mma16816(acc[1][2*p+1], al1, bh[1], bh[3]);
            }
        }

        int gb = ch * 192 + n0w;
        size_t rA = row0 + m0 + (lane >> 2);
#pragma unroll
        for (int rt = 0; rt < 2; ++rt) {
#pragma unroll
            for (int nt = 0; nt < 6; ++nt) {
                int col = gb + nt * 8 + (lane & 3) * 2;
                float2 bv = *(const float2*)(bih + col);
                float* p0 = g_gi + (rA + rt * 16) * G3 + col;
                *(float2*)p0 = make_float2(acc[rt][nt][0] + bv.x, acc[rt][nt][1] + bv.y);
                *(float2*)(p0 + 8 * G3) =
                    make_float2(acc[rt][nt][2] + bv.x, acc[rt][nt][3] + bv.y);
            }
        }
    }
}

// ---------------------------------------------------------------------------
// HMMA GRU scan v2: 256 CTAs x 512 thr x 64 rows. 16 warps = 4/SMSP.
// Warp (rh2 = warp>>3, wg = warp&7): rows rh2*32..+32, gate triplet wg*16..+16.
// smem: Whh_hi @0 (384 rows x 256B, XOR-swizzled chunks) | Whh_lo @98304 |
//       h_hi @196608 (64 x 272B padded) | h_lo @214016.  Total 231424.
// Whh swizzle: 16B chunk c of row g stored at g*256 + (c ^ (g&7))*16
//   -> 8 consecutive rows hit 8 distinct banks: ldmatrix conflict-free.
// ---------------------------------------------------------------------------
constexpr int WH0 = 0, WL0 = 98304, HH0 = 196608, HDL = 17408; // h lo offset from hi
constexpr int SMEM_SCM = 231424;

__global__ __launch_bounds__(512) void scan_mma(
    const float* __restrict__ Whh, const float* __restrict__ bhh,
    float* __restrict__ hid)
{
    extern __shared__ char smc[];
    unsigned sb = smem_u32(smc);
    int tid = threadIdx.x, warp = tid >> 5, lane = tid & 31;
    int m0 = blockIdx.x * 64;

    // Whh split fill into swizzled layout: 384 rows x 16 chunks (16B each)
    for (int idx = tid; idx < 384 * 16; idx += 512) {
        int g = idx >> 4, c = idx & 15;
        const float* src = Whh + (size_t)g * HS + c * 8;
        float4 v0 = *(const float4*)(src);
        float4 v1 = *(const float4*)(src + 4);
        ULL h0, l0, h1, l1;
        split4(v0, h0, l0);
        split4(v1, h1, l1);
        int sw = g * 256 + ((c ^ (g & 7)) << 4);
        *(ULL*)(smc + WH0 + sw)     = h0;
        *(ULL*)(smc + WH0 + sw + 8) = h1;
        *(ULL*)(smc + WL0 + sw)     = l0;
        *(ULL*)(smc + WL0 + sw + 8) = l1;
    }
    // h = 0 (hi+lo: 2*17408 B)
    for (int i = tid; i < 8704; i += 512) ((unsigned*)(smc + HH0))[i] = 0u;

    int rh2 = warp >> 3;         // row half 0/1
    int wg  = warp & 7;          // gate group 0..7
    int lr   = (lane & 7) + ((lane & 8) ? 8 : 0);
    int c0   = (lane & 16) ? 1 : 0;
    unsigned abase = sb + (unsigned)(HH0 + (rh2 * 32 + lr) * PAB + c0 * 16);
    // B row for this lane (per slice s: + s*128)
    int grow = wg * 16 + lr;
    unsigned bRow = sb + (unsigned)(grow * 256);
    int rx = grow & 7;

    int cq = (lane & 3) * 2;
    int rq = lane >> 2;

    float2 biR[2], biZ[2], biN[2];
#pragma unroll
    for (int nt = 0; nt < 2; ++nt) {
        int c = wg * 16 + nt * 8 + cq;
        biR[nt] = *(const float2*)(bhh + c);
        biZ[nt] = *(const float2*)(bhh + 128 + c);
        biN[nt] = *(const float2*)(bhh + 256 + c);
    }

    float2 hreg[2][2][2];   // [mt][rh][nt]
#pragma unroll
    for (int a = 0; a < 2; ++a)
#pragma unroll
        for (int b = 0; b < 2; ++b)
#pragma unroll
            for (int c = 0; c < 2; ++c) hreg[a][b][c] = make_float2(0.0f, 0.0f);

    __syncthreads();

    for (int t = 0; t < Tt; ++t) {
        float acc[2][3][2][4];   // [mt][slice rzn][nt][frag]
#pragma unroll
        for (int a = 0; a < 2; ++a)
#pragma unroll
            for (int s = 0; s < 3; ++s)
#pragma unroll
                for (int n = 0; n < 2; ++n)
#pragma unroll
                    for (int q = 0; q < 4; ++q) acc[a][s][n][q] = 0.0f;

        for (int ks = 0; ks < 8; ++ks) {
            unsigned ka = abase + ks * 32;
            unsigned ah0[4], al0[4], ah1[4], al1[4];
            ldsm4(ah0, ka);
            ldsm4(al0, ka + HDL);
            ldsm4(ah1, ka + 16 * PAB);
            ldsm4(al1, ka + 16 * PAB + HDL);
            unsigned ch = (unsigned)(((2 * ks + c0) ^ rx) << 4);
#pragma unroll
            for (int s = 0; s < 3; ++s) {
                unsigned kb = bRow + (unsigned)(s * 128 * 256) + ch;
                unsigned bh[4], bl[4];
                ldsm4(bh, kb);
                ldsm4(bl, kb + (unsigned)WL0);
                mma16816(acc[0][s][0], ah0, bh[0], bh[2]);
                mma16816(acc[0][s][0], ah0, bl[0], bl[2]);
                mma16816(acc[0][s][0], al0, bh[0], bh[2]);
                mma16816(acc[0][s][1], ah0, bh[1], bh[3]);
                mma16816(acc[0][s][1], ah0, bl[1], bl[3]);
                mma16816(acc[0][s][1], al0, bh[1], bh[3]);
                mma16816(acc[1][s][0], ah1, bh[0], bh[2]);
                mma16816(acc[1][s][0], ah1, bl[0], bl[2]);
                mma16816(acc[1][s][0], al1, bh[0], bh[2]);
                mma16816(acc[1][s][1], ah1, bh[1], bh[3]);
                mma16816(acc[1][s][1], ah1, bl[1], bl[3]);
                mma16816(acc[1][s][1], al1, bh[1], bh[3]);
            }
        }
        __syncthreads();   // all h reads of this step done

#pragma unroll
        for (int mt = 0; mt < 2; ++mt)
#pragma unroll
        for (int rh = 0; rh < 2; ++rh)
#pragma unroll
        for (int nt = 0; nt < 2; ++nt) {
            int m = rh2 * 32 + mt * 16 + rh * 8 + rq;
            int c = wg * 16 + nt * 8 + cq;
            size_t rbase = (size_t)(m0 + m) * Tt + t;
            const float* gp = g_gi + rbase * G3;
            float2 giR = *(const float2*)(gp + c);
            float2 giZ = *(const float2*)(gp + 128 + c);
            float2 giN = *(const float2*)(gp + 256 + c);
            float ghR0 = acc[mt][0][nt][rh*2], ghR1 = acc[mt][0][nt][rh*2+1];
            float ghZ0 = acc[mt][1][nt][rh*2], ghZ1 = acc[mt][1][nt][rh*2+1];
            float ghN0 = acc[mt][2][nt][rh*2], ghN1 = acc[mt][2][nt][rh*2+1];
            float rv0 = sigm(giR.x + ghR0 + biR[nt].x);
            float rv1 = sigm(giR.y + ghR1 + biR[nt].y);
            float zv0 = sigm(giZ.x + ghZ0 + biZ[nt].x);
            float zv1 = sigm(giZ.y + ghZ1 + biZ[nt].y);
            float nv0 = tanh_(giN.x + rv0 * (ghN0 + biN[nt].x));
            float nv1 = tanh_(giN.y + rv1 * (ghN1 + biN[nt].y));
            float hn0 = (1.0f - zv0) * nv0 + zv0 * hreg[mt][rh][nt].x;
            float hn1 = (1.0f - zv1) * nv1 + zv1 * hreg[mt][rh][nt].y;
            hreg[mt][rh][nt] = make_float2(hn0, hn1);
            *(float2*)(g_ys + rbase * HS + c) = hreg[mt][rh][nt];
            unsigned short l0v, l1v;
            unsigned short h0v = split1(hn0, l0v);
            unsigned short h1v = split1(hn1, l1v);
            int off = m * PAB + c * 2;
            *(unsigned*)(smc + HH0 + off)       = (unsigned)h0v | ((unsigned)h1v << 16);
            *(unsigned*)(smc + HH0 + HDL + off) = (unsigned)l0v | ((unsigned)l1v << 16);
        }
        __syncthreads();   // h_new visible for next step
    }

    // hidden output: rows m%8==7 -> rq==7 threads own them
    if (rq == 7) {
#pragma unroll
        for (int mt = 0; mt < 2; ++mt)
#pragma unroll
        for (int rh = 0; rh < 2; ++rh)
#pragma unroll
        for (int nt = 0; nt < 2; ++nt) {
            int m = rh2 * 32 + mt * 16 + rh * 8 + 7;
            int b = (m0 + m) >> 3;
            int c = wg * 16 + nt * 8 + cq;
            *(float2*)(hid + (size_t)b * HS + c) = hreg[mt][rh][nt];
        }
    }
}

// ---------------------------------------------------------------------------
// gi GEMM layer 0 (fused embedding), fp32 f32x2 path (verified)
// ---------------------------------------------------------------------------
__global__ __launch_bounds__(256) void gi_gemm64(
    const float* __restrict__ Wih, const float* __restrict__ bih,
    const float* __restrict__ x,   const float* __restrict__ pea,
    const float* __restrict__ pet, const float* __restrict__ embW,
    const float* __restrict__ embB)
{
    constexpr int K = 64;
    extern __shared__ float sm[];
    float* Wt = sm;
    float* xT = sm + K * WTP;

    int tid = threadIdx.x;
    for (int g = tid; g < G3; g += 256) {
        const float* src = Wih + (size_t)g * K;
#pragma unroll 4
        for (int k0 = 0; k0 < K; k0 += 4) {
            float4 w = *(const float4*)(src + k0);
            Wt[(k0 + 0) * WTP + g] = w.x;
            Wt[(k0 + 1) * WTP + g] = w.y;
            Wt[(k0 + 2) * WTP + g] = w.z;
            Wt[(k0 + 3) * WTP + g] = w.w;
        }
    }

    int warp = tid >> 5, l = tid & 31;
    int row0 = blockIdx.x * 64;

    ULL acc[3][8][2];
#pragma unroll
    for (int g = 0; g < 3; ++g)
#pragma unroll
        for (int j = 0; j < 8; ++j) { acc[g][j][0] = 0ULL; acc[g][j][1] = 0ULL; }

    __syncthreads();
    for (int idx = tid; idx < 64 * 16; idx += 256) {
        int r = idx >> 4, kq = idx & 15;
        int row = row0 + r;
        int t = row % Tt;
        int n = (row / Tt) & 7;
        float pe = __ldg(pet + t) + __ldg(pea + n);
        float2 xv = *(const float2*)(x + (size_t)row * 2);
        float x0 = xv.x + pe, x1 = xv.y + pe;
        float4 w0 = __ldg((const float4*)(embW + 8 * kq));
        float4 w1 = __ldg((const float4*)(embW + 8 * kq + 4));
        float4 b4 = __ldg((const float4*)(embB + 4 * kq));
        float4 v;
        v.x = fmaxf(fmaf(x0, w0.x, fmaf(x1, w0.y, b4.x)), 0.0f);
        v.y = fmaxf(fmaf(x0, w0.z, fmaf(x1, w0.w, b4.y)), 0.0f);
        v.z = fmaxf(fmaf(x0, w1.x, fmaf(x1, w1.y, b4.z)), 0.0f);
        v.w = fmaxf(fmaf(x0, w1.z, fmaf(x1, w1.w, b4.w)), 0.0f);
        float* d = xT + r * XP + 8 * kq;
        *(float4*)(d)     = make_float4(v.x, v.x, v.y, v.y);
        *(float4*)(d + 4) = make_float4(v.z, v.z, v.w, v.w);
    }
    __syncthreads();

#pragma unroll 4
    for (int k2 = 0; k2 < 32; ++k2) {
        const float* wb = Wt + (size_t)(2 * k2) * WTP + 4 * l;
        ulonglong2 wA0 = *(const ulonglong2*)(wb);
        ulonglong2 wA1 = *(const ulonglong2*)(wb + 128);
        ulonglong2 wA2 = *(const ulonglong2*)(wb + 256);
        ulonglong2 wB0 = *(const ulonglong2*)(wb + WTP);
        ulonglong2 wB1 = *(const ulonglong2*)(wb + WTP + 128);
        ulonglong2 wB2 = *(const ulonglong2*)(wb + WTP + 256);
        const float* hb = xT + (warp * 8) * XP + 4 * k2;
#pragma unroll
        for (int j = 0; j < 8; ++j) {
            ulonglong2 h = *(const ulonglong2*)(hb + j * XP);
            fma2(acc[0][j][0], h.x, wA0.x); fma2(acc[0][j][1], h.x, wA0.y);
            fma2(acc[1][j][0], h.x, wA1.x); fma2(acc[1][j][1], h.x, wA1.y);
            fma2(acc[2][j][0], h.x, wA2.x); fma2(acc[2][j][1], h.x, wA2.y);
            fma2(acc[0][j][0], h.y, wB0.x); fma2(acc[0][j][1], h.y, wB0.y);
            fma2(acc[1][j][0], h.y, wB1.x); fma2(acc[1][j][1], h.y, wB1.y);
            fma2(acc[2][j][0], h.y, wB2.x); fma2(acc[2][j][1], h.y, wB2.y);
        }
    }

#pragma unroll
    for (int g = 0; g < 3; ++g) {
        float4 b4 = __ldg((const float4*)(bih + g * 128 + 4 * l));
#pragma unroll
        for (int j = 0; j < 8; ++j) {
            float2 p0 = unpk(acc[g][j][0]);
            float2 p1 = unpk(acc[g][j][1]);
            float4 o = make_float4(p0.x + b4.x, p0.y + b4.y, p1.x + b4.z, p1.y + b4.w);
            *(float4*)(g_gi + (size_t)(row0 + warp * 8 + j) * G3 + g * 128 + 4 * l) = o;
        }
    }
}

// ---------------------------------------------------------------------------
__global__ __launch_bounds__(256) void out_kernel(
    const float* __restrict__ oW, const float* __restrict__ ob,
    float* __restrict__ out)
{
    __shared__ float sW[128 * 64];
    int tid = threadIdx.x;
    for (int idx = tid; idx < 64 * 128; idx += 256) {
        int e = idx >> 7, k = idx & 127;
        sW[k * 64 + e] = oW[idx];
    }
    __syncthreads();
    int gid = blockIdx.x * 256 + tid;
    int e = gid & 63;
    int m = gid >> 6;
    const float* ys = g_ys + ((size_t)m * Tt + (Tt - 1)) * HS;
    float acc = ob[e];
#pragma unroll 8
    for (int k = 0; k < 128; ++k) acc = fmaf(ys[k], sW[k * 64 + e], acc);
    out[gid] = acc;
}

// ---------------------------------------------------------------------------
extern "C" void kernel_launch(void* const* d_in, const int* in_sizes, int n_in,
                              void* d_out, int out_size) {
    const float* x    = (const float*)d_in[0];
    const float* pea  = (const float*)d_in[1];
    const float* pet  = (const float*)d_in[2];
    const float* embW = (const float*)d_in[3];
    const float* embB = (const float*)d_in[4];
    const float* Wih0 = (const float*)d_in[5];
    const float* WihR = (const float*)d_in[6];
    const float* Whh  = (const float*)d_in[7];
    const float* bih  = (const float*)d_in[8];
    const float* bhh  = (const float*)d_in[9];
    const float* outW = (const float*)d_in[10];
    const float* outB = (const float*)d_in[11];

    float* out = (float*)d_out;
    float* hid = out + OUT0;

    const int smem64 = 64 * WTP * 4 + 64 * XP * 4;   // 132096
    cudaFuncSetAttribute(gi_gemm64, cudaFuncAttributeMaxDynamicSharedMemorySize, smem64);
    cudaFuncSetAttribute(gi_mma,    cudaFuncAttributeMaxDynamicSharedMemorySize, SMEM_MMA);
    cudaFuncSetAttribute(scan_mma,  cudaFuncAttributeMaxDynamicSharedMemorySize, SMEM_SCM);

    gi_gemm64<<<RT / 64, 256, smem64>>>(Wih0, bih, x, pea, pet, embW, embB);
    scan_mma<<<Mm / 64, 512, SMEM_SCM>>>(Whh, bhh, hid);

    gi_mma<<<RT / 128, 512, SMEM_MMA>>>(WihR, bih + G3);
    scan_mma<<<Mm / 64, 512, SMEM_SCM>>>(Whh + (size_t)G3 * HS, bhh + G3,
                                         hid + (size_t)Bb * HS);

    gi_mma<<<RT / 128, 512, SMEM_MMA>>>(WihR + (size_t)G3 * HS, bih + 2 * G3);
    scan_mma<<<Mm / 64, 512, SMEM_SCM>>>(Whh + (size_t)2 * G3 * HS, bhh + 2 * G3,
                                         hid + (size_t)2 * Bb * HS);

    out_kernel<<<(Mm * 64) / 256, 256>>>(outW, outB, out);
}